// round 11
// baseline (speedup 1.0000x reference)
#include <cuda_runtime.h>
#include <cuda_bf16.h>
#include <math.h>
#include <stdint.h>

// Problem constants
#define F_IN   256
#define NTREES 512
#define DEPTH  6
#define TDIM   3
#define BATCH  512
#define NCOLS  (NTREES * DEPTH)   // 3072
#define KS     512                // stored K: [hi || lo]
#define KV     768                // virtual K in GEMM: hi.hi + lo.hi + hi.lo

// Scratch (device globals)
__device__ __nv_bfloat16 g_A[NCOLS * KS];   // W^T: [n][k]=hi, [n][256+k]=lo
__device__ __nv_bfloat16 g_B[BATCH * KS];   // in : [b][k]=hi, [b][256+k]=lo
__device__ float g_tl[NCOLS * BATCH];       // thresholded logits [3072][512]

// ---------------------------------------------------------------------------
// Portable tensor-path helpers (sm_80+ baseline; ptxas targets plain sm_103)
// ---------------------------------------------------------------------------
__device__ __forceinline__ uint32_t smem_u32(const void* p) {
    uint32_t a;
    asm("{ .reg .u64 t; cvta.to.shared.u64 t, %1; cvt.u32.u64 %0, t; }" : "=r"(a) : "l"(p));
    return a;
}
__device__ __forceinline__ void cpa16(uint32_t dst, const void* src) {
    asm volatile("cp.async.cg.shared.global [%0], [%1], 16;" :: "r"(dst), "l"(src));
}
__device__ __forceinline__ void ldsm4(uint32_t* r, uint32_t addr) {
    asm volatile("ldmatrix.sync.aligned.m8n8.x4.shared.b16 {%0,%1,%2,%3}, [%4];"
                 : "=r"(r[0]), "=r"(r[1]), "=r"(r[2]), "=r"(r[3]) : "r"(addr));
}
__device__ __forceinline__ void mma16816(float* c, const uint32_t* a,
                                         uint32_t b0, uint32_t b1) {
    asm volatile(
        "mma.sync.aligned.m16n8k16.row.col.f32.bf16.bf16.f32 "
        "{%0,%1,%2,%3}, {%4,%5,%6,%7}, {%8,%9}, {%0,%1,%2,%3};"
        : "+f"(c[0]), "+f"(c[1]), "+f"(c[2]), "+f"(c[3])
        : "r"(a[0]), "r"(a[1]), "r"(a[2]), "r"(a[3]), "r"(b0), "r"(b1));
}
// 128B-row XOR swizzle: 16B chunk index ^= (row & 7)
__device__ __forceinline__ uint32_t swz(uint32_t base, int row, int kbyte) {
    uint32_t off = (uint32_t)(row * 128 + kbyte);
    return base + (off ^ ((off >> 3) & 0x70));
}

// ---------------------------------------------------------------------------
// Kernel 1: fused prep.
// Blocks [0, 192): exact 1.5-entmax -> g_A [hi || lo].
//   Newton on g(tau)=sum relu(z-tau)^2-1 (convex => monotone from tau0=-1).
//   8-lane group owns a column (32 elems/lane in registers); the per-iter
//   sums use 4 INDEPENDENT accumulator pairs to break the serial FMA chain
//   (depth 32 -> 8), then a 3-level group shuffle reduction + fast divide.
// Blocks [192, 448): split input fp32 -> g_B [hi || lo].
// ---------------------------------------------------------------------------
#define CPB 16
#define ENT_BLOCKS (NCOLS / CPB)          // 192
#define SPL_BLOCKS (BATCH * F_IN / 512)   // 256

__global__ void __launch_bounds__(128, 8)
prep_kernel(const float* __restrict__ fa,
            const float* __restrict__ input)
{
    const int tid = threadIdx.x;

    if (blockIdx.x >= ENT_BLOCKS) {
        // ---- split input: [hi || lo] rows of g_B ----
        int i = (blockIdx.x - ENT_BLOCKS) * 128 + tid;  // float4 units
        int b = i >> 6;
        int r = i & 63;                                  // k = 4*r
        float4 v = ((const float4*)input)[i];
        __nv_bfloat162 h01 = __float22bfloat162_rn(make_float2(v.x, v.y));
        __nv_bfloat162 h23 = __float22bfloat162_rn(make_float2(v.z, v.w));
        __nv_bfloat162 l01 = __float22bfloat162_rn(make_float2(
            v.x - __bfloat162float(h01.x), v.y - __bfloat162float(h01.y)));
        __nv_bfloat162 l23 = __float22bfloat162_rn(make_float2(
            v.z - __bfloat162float(h23.x), v.w - __bfloat162float(h23.y)));
        __nv_bfloat16* rowp = g_B + b * KS + r * 4;
        *(uint2*)rowp         = make_uint2(*(uint32_t*)&h01, *(uint32_t*)&h23);
        *(uint2*)(rowp + 256) = make_uint2(*(uint32_t*)&l01, *(uint32_t*)&l23);
        return;
    }

    // ---- entmax ----
    __shared__ float s[CPB][260];   // [col][k], row stride 260 (16B-aligned)

    const int c0   = blockIdx.x * CPB;
    const int lane = tid & 31;
    const int w    = tid >> 5;

    // coalesced load, transposed store
    #pragma unroll
    for (int i = 0; i < 32; i++) {
        int e = tid + i * 128;
        int c = e & 15;
        int r = e >> 4;
        s[c][r] = 0.5f * fa[r * NCOLS + c0 + c];
    }
    __syncthreads();

    const int grp = lane >> 3;      // 0..3: column group within warp
    const int gl  = lane & 7;       // lane within group
    const int col = 4 * w + grp;    // local column 0..15

    // 32 elements per lane: k = 32*m + 4*gl + t
    float4 z4[8];
    #pragma unroll
    for (int m = 0; m < 8; m++)
        z4[m] = *(const float4*)&s[col][m * 32 + gl * 4];

    // column max: 4 independent partial maxes, then 3 butterfly levels
    {
        float m0 = fmaxf(fmaxf(z4[0].x, z4[0].y), fmaxf(z4[0].z, z4[0].w));
        float m1 = fmaxf(fmaxf(z4[1].x, z4[1].y), fmaxf(z4[1].z, z4[1].w));
        float m2 = fmaxf(fmaxf(z4[2].x, z4[2].y), fmaxf(z4[2].z, z4[2].w));
        float m3 = fmaxf(fmaxf(z4[3].x, z4[3].y), fmaxf(z4[3].z, z4[3].w));
        #pragma unroll
        for (int m = 4; m < 8; m++) {
            float t0 = fmaxf(fmaxf(z4[m].x, z4[m].y), fmaxf(z4[m].z, z4[m].w));
            if (m == 4) m0 = fmaxf(m0, t0);
            else if (m == 5) m1 = fmaxf(m1, t0);
            else if (m == 6) m2 = fmaxf(m2, t0);
            else m3 = fmaxf(m3, t0);
        }
        float mx = fmaxf(fmaxf(m0, m1), fmaxf(m2, m3));
        #pragma unroll
        for (int off = 4; off > 0; off >>= 1)
            mx = fmaxf(mx, __shfl_xor_sync(0xffffffffu, mx, off));
        #pragma unroll
        for (int m = 0; m < 8; m++) {
            z4[m].x -= mx; z4[m].y -= mx; z4[m].z -= mx; z4[m].w -= mx;
        }
    }

    // Newton: tau0 = -1; monotone from below; 4 accumulator pairs for ILP.
    float tau = -1.0f;
    for (int it = 0; it < 12; it++) {
        float s1p[4] = {0.0f, 0.0f, 0.0f, 0.0f};
        float s2p[4] = {0.0f, 0.0f, 0.0f, 0.0f};
        #pragma unroll
        for (int m = 0; m < 8; m++) {
            const int p = m & 3;
            float d0 = fmaxf(z4[m].x - tau, 0.0f);
            float d1 = fmaxf(z4[m].y - tau, 0.0f);
            float d2 = fmaxf(z4[m].z - tau, 0.0f);
            float d3 = fmaxf(z4[m].w - tau, 0.0f);
            s1p[p] += (d0 + d1) + (d2 + d3);
            float t01 = fmaf(d1, d1, d0 * d0);
            float t23 = fmaf(d3, d3, d2 * d2);
            s2p[p] += t01 + t23;
        }
        float s1 = (s1p[0] + s1p[1]) + (s1p[2] + s1p[3]);
        float s2 = (s2p[0] + s2p[1]) + (s2p[2] + s2p[3]);
        #pragma unroll
        for (int off = 4; off > 0; off >>= 1) {
            s1 += __shfl_xor_sync(0xffffffffu, s1, off);
            s2 += __shfl_xor_sync(0xffffffffu, s2, off);
        }
        tau += __fdividef(s2 - 1.0f, 2.0f * s1);
    }

    // emit [hi || lo] rows of g_A, packed bf16x2 (STG.64)
    __nv_bfloat16* Arow = g_A + (size_t)(c0 + col) * KS;
    #pragma unroll
    for (int m = 0; m < 8; m++) {
        float d0 = fmaxf(z4[m].x - tau, 0.0f);
        float d1 = fmaxf(z4[m].y - tau, 0.0f);
        float d2 = fmaxf(z4[m].z - tau, 0.0f);
        float d3 = fmaxf(z4[m].w - tau, 0.0f);
        float w0 = d0 * d0, w1 = d1 * d1, w2 = d2 * d2, w3 = d3 * d3;
        __nv_bfloat162 h01 = __float22bfloat162_rn(make_float2(w0, w1));
        __nv_bfloat162 h23 = __float22bfloat162_rn(make_float2(w2, w3));
        __nv_bfloat162 l01 = __float22bfloat162_rn(make_float2(
            w0 - __bfloat162float(h01.x), w1 - __bfloat162float(h01.y)));
        __nv_bfloat162 l23 = __float22bfloat162_rn(make_float2(
            w2 - __bfloat162float(h23.x), w3 - __bfloat162float(h23.y)));
        int k = m * 32 + gl * 4;
        *(uint2*)(Arow + k)       = make_uint2(*(uint32_t*)&h01, *(uint32_t*)&h23);
        *(uint2*)(Arow + 256 + k) = make_uint2(*(uint32_t*)&l01, *(uint32_t*)&l23);
    }
}

// ---------------------------------------------------------------------------
// Kernel 2: HMMA bf16 GEMM over virtual K=768:
//   kc 0-3:  A hi x B hi;  kc 4-7: A lo x B hi;  kc 8-11: A hi x B lo
// (drops only loA.loB ~ 2^-18). Stored arrays are [hi||lo], 512 wide.
// ---------------------------------------------------------------------------
#define CK 64
#define NKC (KV / CK)    // 12

#define SA0 0
#define SA1 16384
#define SB0 32768
#define SB1 40960
#define SM_TOTAL 49152

__device__ __forceinline__ int map_kcA(int kc) { return kc < 8 ? kc : kc - 8; }
__device__ __forceinline__ int map_kcB(int kc) { return kc < 4 ? kc : kc - 4; }

__device__ __forceinline__ void load_A_chunk(uint32_t sbase, int n0, int kcA, int tid)
{
    #pragma unroll
    for (int j = 0; j < 4; j++) {
        int e = tid + j * 256;
        int row = e >> 3;
        int ch  = e & 7;
        cpa16(swz(sbase, row, ch * 16),
              g_A + (size_t)(n0 + row) * KS + kcA * CK + ch * 8);
    }
}
__device__ __forceinline__ void load_B_chunk(uint32_t sbase, int b0, int kcB, int tid)
{
    #pragma unroll
    for (int j = 0; j < 2; j++) {
        int e = tid + j * 256;
        int row = e >> 3;
        int ch  = e & 7;
        cpa16(swz(sbase, row, ch * 16),
              g_B + (size_t)(b0 + row) * KS + kcB * CK + ch * 8);
    }
}

__global__ void __launch_bounds__(256, 2)
gemm_hmma_kernel(const float* __restrict__ thr,
                 const float* __restrict__ ltemp)
{
    extern __shared__ char smem[];
    const uint32_t sb = smem_u32(smem);
    const int tid  = threadIdx.x;
    const int lane = tid & 31;
    const int wid  = tid >> 5;
    const int wm   = wid >> 1;
    const int wn   = wid & 1;

    const int n0 = blockIdx.x * 128;
    const int b0 = blockIdx.y * 64;

    const uint32_t sA[2] = {sb + SA0, sb + SA1};
    const uint32_t sB[2] = {sb + SB0, sb + SB1};

    float acc[2][4][4];
    #pragma unroll
    for (int mi = 0; mi < 2; mi++)
        #pragma unroll
        for (int ni = 0; ni < 4; ni++)
            #pragma unroll
            for (int q = 0; q < 4; q++) acc[mi][ni][q] = 0.0f;

    load_A_chunk(sA[0], n0, map_kcA(0), tid);
    load_B_chunk(sB[0], b0, map_kcB(0), tid);
    asm volatile("cp.async.commit_group;");

    const int lane15 = lane & 15;
    const int khalf  = (lane >> 4) * 16;

    int buf = 0;
    for (int kc = 0; kc < NKC; kc++) {
        if (kc + 1 < NKC) {
            load_A_chunk(sA[buf ^ 1], n0, map_kcA(kc + 1), tid);
            load_B_chunk(sB[buf ^ 1], b0, map_kcB(kc + 1), tid);
            asm volatile("cp.async.commit_group;");
            asm volatile("cp.async.wait_group 1;");
        } else {
            asm volatile("cp.async.wait_group 0;");
        }
        __syncthreads();

        #pragma unroll
        for (int ks = 0; ks < 4; ks++) {
            const int kbyte = ks * 32 + khalf;
            uint32_t a0[4], a1[4], bq0[4], bq1[4];
            ldsm4(a0,  swz(sA[buf], wm * 32 + lane15,      kbyte));
            ldsm4(a1,  swz(sA[buf], wm * 32 + 16 + lane15, kbyte));
            ldsm4(bq0, swz(sB[buf], wn * 32 + lane15,      kbyte));
            ldsm4(bq1, swz(sB[buf], wn * 32 + 16 + lane15, kbyte));

            mma16816(acc[0][0], a0, bq0[0], bq0[2]);
            mma16816(acc[0][1], a0, bq0[1], bq0[3]);
            mma16816(acc[0][2], a0, bq1[0], bq1[2]);
            mma16816(acc[0][3], a0, bq1[1], bq1[3]);
            mma16816(acc[1][0], a1, bq0[0], bq0[2]);
            mma16816(acc[1][1], a1, bq0[1], bq0[3]);
            mma16816(acc[1][2], a1, bq1[0], bq1[2]);
            mma16816(acc[1][3], a1, bq1[1], bq1[3]);
        }
        __syncthreads();
        buf ^= 1;
    }

    const int qr = lane >> 2;
    const int qc = (lane & 3) * 2;
    #pragma unroll
    for (int mi = 0; mi < 2; mi++) {
        const int nr0 = n0 + wm * 32 + mi * 16 + qr;
        const int nr1 = nr0 + 8;
        const int t0 = nr0 / DEPTH, d0 = nr0 % DEPTH;
        const int t1 = nr1 / DEPTH, d1 = nr1 % DEPTH;
        const float th0 = thr[t0 * DEPTH + d0];
        const float sc0 = expf(-ltemp[t0 * DEPTH + d0]);
        const float th1 = thr[t1 * DEPTH + d1];
        const float sc1 = expf(-ltemp[t1 * DEPTH + d1]);
        #pragma unroll
        for (int ni = 0; ni < 4; ni++) {
            const int bc = b0 + wn * 32 + ni * 8 + qc;
            float2 v0, v1;
            v0.x = (acc[mi][ni][0] - th0) * sc0;
            v0.y = (acc[mi][ni][1] - th0) * sc0;
            v1.x = (acc[mi][ni][2] - th1) * sc1;
            v1.y = (acc[mi][ni][3] - th1) * sc1;
            *(float2*)&g_tl[(size_t)nr0 * BATCH + bc] = v0;
            *(float2*)&g_tl[(size_t)nr1 * BATCH + bc] = v1;
        }
    }
}

// ---------------------------------------------------------------------------
// Kernel 3: one (tree, batch) pair per thread. Block = 8 trees x 32 batches.
// ---------------------------------------------------------------------------
#define TT 8    // trees per block
#define BB 32   // batches per block

__global__ void __launch_bounds__(256, 4)
leaf_kernel(const float* __restrict__ response,  // [512][3][64]
            float* __restrict__ out)             // [512][1536]
{
    __shared__ float4 rsp4[TT * 48];
    __shared__ float  sout[BB][TT * 3 + 3];

    const int t0   = blockIdx.x * TT;
    const int b0   = blockIdx.y * BB;
    const int tid  = threadIdx.x;
    const int lane = tid & 31;
    const int w    = tid >> 5;

    for (int i = tid; i < TT * 48; i += 256)
        rsp4[i] = ((const float4*)response)[(size_t)t0 * 48 + i];
    __syncthreads();

    const int t = t0 + w;
    const int b = b0 + lane;

    float a[DEPTH], bb[DEPTH];
    #pragma unroll
    for (int d = 0; d < DEPTH; d++) {
        float v = g_tl[(size_t)(t * DEPTH + d) * BATCH + b];
        float x = 0.5f * v;
        a[d]  = fminf(fmaxf(0.5f + x, -0.5f), 1.5f);
        bb[d] = fminf(fmaxf(0.5f - x, -0.5f), 1.5f);
    }

    float w8[8];
    w8[0] = 1.0f;
    #pragma unroll
    for (int d = 0; d < 3; d++) {
        const int sz = 1 << d;
        #pragma unroll
        for (int i = sz - 1; i >= 0; i--) {
            w8[i + sz] = w8[i] * bb[d];
            w8[i]      = w8[i] * a[d];
        }
    }
    float q8[8];
    q8[0] = 1.0f;
    #pragma unroll
    for (int e = 0; e < 3; e++) {
        const int sz = 1 << e;
        #pragma unroll
        for (int i = sz - 1; i >= 0; i--) {
            q8[i + sz] = q8[i] * bb[3 + e];
            q8[i]      = q8[i] * a[3 + e];
        }
    }

    const float4* rp = &rsp4[w * 48];
    float o0 = 0.0f, o1 = 0.0f, o2 = 0.0f;
    #pragma unroll
    for (int j = 0; j < 8; j++) {
        float4 r00 = rp[j * 2],      r01 = rp[j * 2 + 1];
        float4 r10 = rp[16 + j * 2], r11 = rp[16 + j * 2 + 1];
        float4 r20 = rp[32 + j * 2], r21 = rp[32 + j * 2 + 1];
        float s0 = w8[0]*r00.x + w8[1]*r00.y + w8[2]*r00.z + w8[3]*r00.w
                 + w8[4]*r01.x + w8[5]*r01.y + w8[6]*r01.z + w8[7]*r01.w;
        float s1 = w8[0]*r10.x + w8[1]*r10.y + w8[2]*r10.z + w8[3]*r10.w
                 + w8[4]*r11.x + w8[5]*r11.y + w8[6]*r11.z + w8[7]*r11.w;
        float s2 = w8[0]*r20.x + w8[1]*r20.y + w8[2]*r20.z + w8[3]*r20.w
                 + w8[4]*r21.x + w8[5]*r21.y + w8[6]*r21.z + w8[7]*r21.w;
        o0 = fmaf(q8[j], s0, o0);
        o1 = fmaf(q8[j], s1, o1);
        o2 = fmaf(q8[j], s2, o2);
    }

    sout[lane][w * 3 + 0] = o0;
    sout[lane][w * 3 + 1] = o1;
    sout[lane][w * 3 + 2] = o2;
    __syncthreads();

    if (tid < (BB * TT * 3) / 4) {
        int row = tid / 6;
        int col = tid % 6;
        float4 v;
        v.x = sout[row][col * 4 + 0];
        v.y = sout[row][col * 4 + 1];
        v.z = sout[row][col * 4 + 2];
        v.w = sout[row][col * 4 + 3];
        *(float4*)&out[(size_t)(b0 + row) * (NTREES * TDIM) + t0 * 3 + col * 4] = v;
    }
}

// ---------------------------------------------------------------------------
extern "C" void kernel_launch(void* const* d_in, const int* in_sizes, int n_in,
                              void* d_out, int out_size)
{
    const float* input    = (const float*)d_in[0];  // [512][256]
    const float* fa       = (const float*)d_in[1];  // [256][3072]
    const float* thr      = (const float*)d_in[2];  // [512][6]
    const float* ltemp    = (const float*)d_in[3];  // [512][6]
    const float* response = (const float*)d_in[4];  // [512][3][64]
    float* out = (float*)d_out;                     // [512][1536]

    cudaFuncSetAttribute(gemm_hmma_kernel,
                         cudaFuncAttributeMaxDynamicSharedMemorySize, SM_TOTAL);

    prep_kernel<<<ENT_BLOCKS + SPL_BLOCKS, 128>>>(fa, input);

    dim3 g2(NCOLS / 128, BATCH / 64);
    gemm_hmma_kernel<<<g2, 256, SM_TOTAL>>>(thr, ltemp);

    dim3 g3(NTREES / TT, BATCH / BB);
    leaf_kernel<<<g3, 256>>>(response, out);
}

// round 12
// speedup vs baseline: 1.0099x; 1.0099x over previous
#include <cuda_runtime.h>
#include <cuda_bf16.h>
#include <math.h>
#include <stdint.h>

// Problem constants
#define F_IN   256
#define NTREES 512
#define DEPTH  6
#define TDIM   3
#define BATCH  512
#define NCOLS  (NTREES * DEPTH)   // 3072
#define KS     512                // stored K: [hi || lo]
#define KV     768                // virtual K in GEMM: hi.hi + lo.hi + hi.lo

// Scratch (device globals)
__device__ __nv_bfloat16 g_A[NCOLS * KS];   // W^T: [n][k]=hi, [n][256+k]=lo
__device__ __nv_bfloat16 g_B[BATCH * KS];   // in : [b][k]=hi, [b][256+k]=lo
__device__ float g_tl[NCOLS * BATCH];       // thresholded logits [3072][512]

// ---------------------------------------------------------------------------
// Portable tensor-path helpers (sm_80+ baseline; ptxas targets plain sm_103)
// ---------------------------------------------------------------------------
__device__ __forceinline__ uint32_t smem_u32(const void* p) {
    uint32_t a;
    asm("{ .reg .u64 t; cvta.to.shared.u64 t, %1; cvt.u32.u64 %0, t; }" : "=r"(a) : "l"(p));
    return a;
}
__device__ __forceinline__ void cpa16(uint32_t dst, const void* src) {
    asm volatile("cp.async.cg.shared.global [%0], [%1], 16;" :: "r"(dst), "l"(src));
}
__device__ __forceinline__ void ldsm4(uint32_t* r, uint32_t addr) {
    asm volatile("ldmatrix.sync.aligned.m8n8.x4.shared.b16 {%0,%1,%2,%3}, [%4];"
                 : "=r"(r[0]), "=r"(r[1]), "=r"(r[2]), "=r"(r[3]) : "r"(addr));
}
__device__ __forceinline__ void mma16816(float* c, const uint32_t* a,
                                         uint32_t b0, uint32_t b1) {
    asm volatile(
        "mma.sync.aligned.m16n8k16.row.col.f32.bf16.bf16.f32 "
        "{%0,%1,%2,%3}, {%4,%5,%6,%7}, {%8,%9}, {%0,%1,%2,%3};"
        : "+f"(c[0]), "+f"(c[1]), "+f"(c[2]), "+f"(c[3])
        : "r"(a[0]), "r"(a[1]), "r"(a[2]), "r"(a[3]), "r"(b0), "r"(b1));
}
// 128B-row XOR swizzle: 16B chunk index ^= (row & 7)
__device__ __forceinline__ uint32_t swz(uint32_t base, int row, int kbyte) {
    uint32_t off = (uint32_t)(row * 128 + kbyte);
    return base + (off ^ ((off >> 3) & 0x70));
}

// ---------------------------------------------------------------------------
// Kernel 1: fused prep.
// Blocks [0, 768): exact 1.5-entmax, ONE WARP PER COLUMN -> g_A [hi || lo].
//   Newton on g(tau)=sum relu(z-tau)^2-1 (convex => monotone from tau0=-1).
//   Lane owns k in [8*lane, 8*lane+8): float4 x2 loads, STG.128 x2 stores.
//   3072 warps across 768 blocks => ~20 resident warps/SM hides the
//   shuffle/divide chain (prior layouts had only ~5).
// Blocks [768, 1024): split input fp32 -> g_B [hi || lo].
// ---------------------------------------------------------------------------
#define CPB 4
#define ENT_BLOCKS (NCOLS / CPB)          // 768
#define SPL_BLOCKS (BATCH * F_IN / 512)   // 256

__global__ void __launch_bounds__(128, 8)
prep_kernel(const float* __restrict__ fa,
            const float* __restrict__ input)
{
    const int tid = threadIdx.x;

    if (blockIdx.x >= ENT_BLOCKS) {
        // ---- split input: [hi || lo] rows of g_B ----
        int i = (blockIdx.x - ENT_BLOCKS) * 128 + tid;  // float4 units
        int b = i >> 6;
        int r = i & 63;                                  // k = 4*r
        float4 v = ((const float4*)input)[i];
        __nv_bfloat162 h01 = __float22bfloat162_rn(make_float2(v.x, v.y));
        __nv_bfloat162 h23 = __float22bfloat162_rn(make_float2(v.z, v.w));
        __nv_bfloat162 l01 = __float22bfloat162_rn(make_float2(
            v.x - __bfloat162float(h01.x), v.y - __bfloat162float(h01.y)));
        __nv_bfloat162 l23 = __float22bfloat162_rn(make_float2(
            v.z - __bfloat162float(h23.x), v.w - __bfloat162float(h23.y)));
        __nv_bfloat16* rowp = g_B + b * KS + r * 4;
        *(uint2*)rowp         = make_uint2(*(uint32_t*)&h01, *(uint32_t*)&h23);
        *(uint2*)(rowp + 256) = make_uint2(*(uint32_t*)&l01, *(uint32_t*)&l23);
        return;
    }

    // ---- entmax: warp per column ----
    __shared__ float s[CPB][260];

    const int c0   = blockIdx.x * CPB;
    const int lane = tid & 31;
    const int w    = tid >> 5;       // column within block

    // coalesced-ish load: 1024 elems, transposed into s[c][r]
    #pragma unroll
    for (int i = 0; i < 8; i++) {
        int e = tid + i * 128;
        int c = e & 3;
        int r = e >> 2;
        s[c][r] = 0.5f * fa[r * NCOLS + c0 + c];
    }
    __syncthreads();

    // lane owns k = 8*lane .. 8*lane+7
    float4 za = *(const float4*)&s[w][lane * 8];
    float4 zb = *(const float4*)&s[w][lane * 8 + 4];

    // column max: 2 local trees, then 5 butterfly levels
    float mx = fmaxf(fmaxf(fmaxf(za.x, za.y), fmaxf(za.z, za.w)),
                     fmaxf(fmaxf(zb.x, zb.y), fmaxf(zb.z, zb.w)));
    #pragma unroll
    for (int off = 16; off > 0; off >>= 1)
        mx = fmaxf(mx, __shfl_xor_sync(0xffffffffu, mx, off));
    za.x -= mx; za.y -= mx; za.z -= mx; za.w -= mx;
    zb.x -= mx; zb.y -= mx; zb.z -= mx; zb.w -= mx;

    // Newton: tau0 = -1 (max(z)=0); monotone from below; fast division.
    float tau = -1.0f;
    for (int it = 0; it < 12; it++) {
        float d0 = fmaxf(za.x - tau, 0.0f);
        float d1 = fmaxf(za.y - tau, 0.0f);
        float d2 = fmaxf(za.z - tau, 0.0f);
        float d3 = fmaxf(za.w - tau, 0.0f);
        float d4 = fmaxf(zb.x - tau, 0.0f);
        float d5 = fmaxf(zb.y - tau, 0.0f);
        float d6 = fmaxf(zb.z - tau, 0.0f);
        float d7 = fmaxf(zb.w - tau, 0.0f);
        float s1 = ((d0 + d1) + (d2 + d3)) + ((d4 + d5) + (d6 + d7));
        float p0 = fmaf(d1, d1, d0 * d0);
        float p1 = fmaf(d3, d3, d2 * d2);
        float p2 = fmaf(d5, d5, d4 * d4);
        float p3 = fmaf(d7, d7, d6 * d6);
        float s2 = (p0 + p1) + (p2 + p3);
        #pragma unroll
        for (int off = 16; off > 0; off >>= 1) {
            s1 += __shfl_xor_sync(0xffffffffu, s1, off);
            s2 += __shfl_xor_sync(0xffffffffu, s2, off);
        }
        tau += __fdividef(s2 - 1.0f, 2.0f * s1);
    }

    // emit [hi || lo]: 8 bf16 = 16B per segment -> 2x STG.128, coalesced
    float d0 = fmaxf(za.x - tau, 0.0f);
    float d1 = fmaxf(za.y - tau, 0.0f);
    float d2 = fmaxf(za.z - tau, 0.0f);
    float d3 = fmaxf(za.w - tau, 0.0f);
    float d4 = fmaxf(zb.x - tau, 0.0f);
    float d5 = fmaxf(zb.y - tau, 0.0f);
    float d6 = fmaxf(zb.z - tau, 0.0f);
    float d7 = fmaxf(zb.w - tau, 0.0f);
    float w0 = d0*d0, w1 = d1*d1, w2 = d2*d2, w3 = d3*d3;
    float w4 = d4*d4, w5 = d5*d5, w6 = d6*d6, w7 = d7*d7;

    __nv_bfloat162 h01 = __float22bfloat162_rn(make_float2(w0, w1));
    __nv_bfloat162 h23 = __float22bfloat162_rn(make_float2(w2, w3));
    __nv_bfloat162 h45 = __float22bfloat162_rn(make_float2(w4, w5));
    __nv_bfloat162 h67 = __float22bfloat162_rn(make_float2(w6, w7));
    __nv_bfloat162 l01 = __float22bfloat162_rn(make_float2(
        w0 - __bfloat162float(h01.x), w1 - __bfloat162float(h01.y)));
    __nv_bfloat162 l23 = __float22bfloat162_rn(make_float2(
        w2 - __bfloat162float(h23.x), w3 - __bfloat162float(h23.y)));
    __nv_bfloat162 l45 = __float22bfloat162_rn(make_float2(
        w4 - __bfloat162float(h45.x), w5 - __bfloat162float(h45.y)));
    __nv_bfloat162 l67 = __float22bfloat162_rn(make_float2(
        w6 - __bfloat162float(h67.x), w7 - __bfloat162float(h67.y)));

    __nv_bfloat16* Arow = g_A + (size_t)(c0 + w) * KS;
    uint4 hv = make_uint4(*(uint32_t*)&h01, *(uint32_t*)&h23,
                          *(uint32_t*)&h45, *(uint32_t*)&h67);
    uint4 lv = make_uint4(*(uint32_t*)&l01, *(uint32_t*)&l23,
                          *(uint32_t*)&l45, *(uint32_t*)&l67);
    *(uint4*)(Arow + lane * 8)       = hv;
    *(uint4*)(Arow + 256 + lane * 8) = lv;
}

// ---------------------------------------------------------------------------
// Kernel 2: HMMA bf16 GEMM over virtual K=768:
//   kc 0-3:  A hi x B hi;  kc 4-7: A lo x B hi;  kc 8-11: A hi x B lo
// (drops only loA.loB ~ 2^-18). Stored arrays are [hi||lo], 512 wide.
// ---------------------------------------------------------------------------
#define CK 64
#define NKC (KV / CK)    // 12

#define SA0 0
#define SA1 16384
#define SB0 32768
#define SB1 40960
#define SM_TOTAL 49152

__device__ __forceinline__ int map_kcA(int kc) { return kc < 8 ? kc : kc - 8; }
__device__ __forceinline__ int map_kcB(int kc) { return kc < 4 ? kc : kc - 4; }

__device__ __forceinline__ void load_A_chunk(uint32_t sbase, int n0, int kcA, int tid)
{
    #pragma unroll
    for (int j = 0; j < 4; j++) {
        int e = tid + j * 256;
        int row = e >> 3;
        int ch  = e & 7;
        cpa16(swz(sbase, row, ch * 16),
              g_A + (size_t)(n0 + row) * KS + kcA * CK + ch * 8);
    }
}
__device__ __forceinline__ void load_B_chunk(uint32_t sbase, int b0, int kcB, int tid)
{
    #pragma unroll
    for (int j = 0; j < 2; j++) {
        int e = tid + j * 256;
        int row = e >> 3;
        int ch  = e & 7;
        cpa16(swz(sbase, row, ch * 16),
              g_B + (size_t)(b0 + row) * KS + kcB * CK + ch * 8);
    }
}

__global__ void __launch_bounds__(256, 2)
gemm_hmma_kernel(const float* __restrict__ thr,
                 const float* __restrict__ ltemp)
{
    extern __shared__ char smem[];
    const uint32_t sb = smem_u32(smem);
    const int tid  = threadIdx.x;
    const int lane = tid & 31;
    const int wid  = tid >> 5;
    const int wm   = wid >> 1;
    const int wn   = wid & 1;

    const int n0 = blockIdx.x * 128;
    const int b0 = blockIdx.y * 64;

    const uint32_t sA[2] = {sb + SA0, sb + SA1};
    const uint32_t sB[2] = {sb + SB0, sb + SB1};

    float acc[2][4][4];
    #pragma unroll
    for (int mi = 0; mi < 2; mi++)
        #pragma unroll
        for (int ni = 0; ni < 4; ni++)
            #pragma unroll
            for (int q = 0; q < 4; q++) acc[mi][ni][q] = 0.0f;

    load_A_chunk(sA[0], n0, map_kcA(0), tid);
    load_B_chunk(sB[0], b0, map_kcB(0), tid);
    asm volatile("cp.async.commit_group;");

    const int lane15 = lane & 15;
    const int khalf  = (lane >> 4) * 16;

    int buf = 0;
    for (int kc = 0; kc < NKC; kc++) {
        if (kc + 1 < NKC) {
            load_A_chunk(sA[buf ^ 1], n0, map_kcA(kc + 1), tid);
            load_B_chunk(sB[buf ^ 1], b0, map_kcB(kc + 1), tid);
            asm volatile("cp.async.commit_group;");
            asm volatile("cp.async.wait_group 1;");
        } else {
            asm volatile("cp.async.wait_group 0;");
        }
        __syncthreads();

        #pragma unroll
        for (int ks = 0; ks < 4; ks++) {
            const int kbyte = ks * 32 + khalf;
            uint32_t a0[4], a1[4], bq0[4], bq1[4];
            ldsm4(a0,  swz(sA[buf], wm * 32 + lane15,      kbyte));
            ldsm4(a1,  swz(sA[buf], wm * 32 + 16 + lane15, kbyte));
            ldsm4(bq0, swz(sB[buf], wn * 32 + lane15,      kbyte));
            ldsm4(bq1, swz(sB[buf], wn * 32 + 16 + lane15, kbyte));

            mma16816(acc[0][0], a0, bq0[0], bq0[2]);
            mma16816(acc[0][1], a0, bq0[1], bq0[3]);
            mma16816(acc[0][2], a0, bq1[0], bq1[2]);
            mma16816(acc[0][3], a0, bq1[1], bq1[3]);
            mma16816(acc[1][0], a1, bq0[0], bq0[2]);
            mma16816(acc[1][1], a1, bq0[1], bq0[3]);
            mma16816(acc[1][2], a1, bq1[0], bq1[2]);
            mma16816(acc[1][3], a1, bq1[1], bq1[3]);
        }
        __syncthreads();
        buf ^= 1;
    }

    const int qr = lane >> 2;
    const int qc = (lane & 3) * 2;
    #pragma unroll
    for (int mi = 0; mi < 2; mi++) {
        const int nr0 = n0 + wm * 32 + mi * 16 + qr;
        const int nr1 = nr0 + 8;
        const int t0 = nr0 / DEPTH, d0 = nr0 % DEPTH;
        const int t1 = nr1 / DEPTH, d1 = nr1 % DEPTH;
        const float th0 = thr[t0 * DEPTH + d0];
        const float sc0 = expf(-ltemp[t0 * DEPTH + d0]);
        const float th1 = thr[t1 * DEPTH + d1];
        const float sc1 = expf(-ltemp[t1 * DEPTH + d1]);
        #pragma unroll
        for (int ni = 0; ni < 4; ni++) {
            const int bc = b0 + wn * 32 + ni * 8 + qc;
            float2 v0, v1;
            v0.x = (acc[mi][ni][0] - th0) * sc0;
            v0.y = (acc[mi][ni][1] - th0) * sc0;
            v1.x = (acc[mi][ni][2] - th1) * sc1;
            v1.y = (acc[mi][ni][3] - th1) * sc1;
            *(float2*)&g_tl[(size_t)nr0 * BATCH + bc] = v0;
            *(float2*)&g_tl[(size_t)nr1 * BATCH + bc] = v1;
        }
    }
}

// ---------------------------------------------------------------------------
// Kernel 3: one (tree, batch) pair per thread. Block = 8 trees x 32 batches.
// ---------------------------------------------------------------------------
#define TT 8    // trees per block
#define BB 32   // batches per block

__global__ void __launch_bounds__(256, 4)
leaf_kernel(const float* __restrict__ response,  // [512][3][64]
            float* __restrict__ out)             // [512][1536]
{
    __shared__ float4 rsp4[TT * 48];
    __shared__ float  sout[BB][TT * 3 + 3];

    const int t0   = blockIdx.x * TT;
    const int b0   = blockIdx.y * BB;
    const int tid  = threadIdx.x;
    const int lane = tid & 31;
    const int w    = tid >> 5;

    for (int i = tid; i < TT * 48; i += 256)
        rsp4[i] = ((const float4*)response)[(size_t)t0 * 48 + i];
    __syncthreads();

    const int t = t0 + w;
    const int b = b0 + lane;

    float a[DEPTH], bb[DEPTH];
    #pragma unroll
    for (int d = 0; d < DEPTH; d++) {
        float v = g_tl[(size_t)(t * DEPTH + d) * BATCH + b];
        float x = 0.5f * v;
        a[d]  = fminf(fmaxf(0.5f + x, -0.5f), 1.5f);
        bb[d] = fminf(fmaxf(0.5f - x, -0.5f), 1.5f);
    }

    float w8[8];
    w8[0] = 1.0f;
    #pragma unroll
    for (int d = 0; d < 3; d++) {
        const int sz = 1 << d;
        #pragma unroll
        for (int i = sz - 1; i >= 0; i--) {
            w8[i + sz] = w8[i] * bb[d];
            w8[i]      = w8[i] * a[d];
        }
    }
    float q8[8];
    q8[0] = 1.0f;
    #pragma unroll
    for (int e = 0; e < 3; e++) {
        const int sz = 1 << e;
        #pragma unroll
        for (int i = sz - 1; i >= 0; i--) {
            q8[i + sz] = q8[i] * bb[3 + e];
            q8[i]      = q8[i] * a[3 + e];
        }
    }

    const float4* rp = &rsp4[w * 48];
    float o0 = 0.0f, o1 = 0.0f, o2 = 0.0f;
    #pragma unroll
    for (int j = 0; j < 8; j++) {
        float4 r00 = rp[j * 2],      r01 = rp[j * 2 + 1];
        float4 r10 = rp[16 + j * 2], r11 = rp[16 + j * 2 + 1];
        float4 r20 = rp[32 + j * 2], r21 = rp[32 + j * 2 + 1];
        float s0 = w8[0]*r00.x + w8[1]*r00.y + w8[2]*r00.z + w8[3]*r00.w
                 + w8[4]*r01.x + w8[5]*r01.y + w8[6]*r01.z + w8[7]*r01.w;
        float s1 = w8[0]*r10.x + w8[1]*r10.y + w8[2]*r10.z + w8[3]*r10.w
                 + w8[4]*r11.x + w8[5]*r11.y + w8[6]*r11.z + w8[7]*r11.w;
        float s2 = w8[0]*r20.x + w8[1]*r20.y + w8[2]*r20.z + w8[3]*r20.w
                 + w8[4]*r21.x + w8[5]*r21.y + w8[6]*r21.z + w8[7]*r21.w;
        o0 = fmaf(q8[j], s0, o0);
        o1 = fmaf(q8[j], s1, o1);
        o2 = fmaf(q8[j], s2, o2);
    }

    sout[lane][w * 3 + 0] = o0;
    sout[lane][w * 3 + 1] = o1;
    sout[lane][w * 3 + 2] = o2;
    __syncthreads();

    if (tid < (BB * TT * 3) / 4) {
        int row = tid / 6;
        int col = tid % 6;
        float4 v;
        v.x = sout[row][col * 4 + 0];
        v.y = sout[row][col * 4 + 1];
        v.z = sout[row][col * 4 + 2];
        v.w = sout[row][col * 4 + 3];
        *(float4*)&out[(size_t)(b0 + row) * (NTREES * TDIM) + t0 * 3 + col * 4] = v;
    }
}

// ---------------------------------------------------------------------------
extern "C" void kernel_launch(void* const* d_in, const int* in_sizes, int n_in,
                              void* d_out, int out_size)
{
    const float* input    = (const float*)d_in[0];  // [512][256]
    const float* fa       = (const float*)d_in[1];  // [256][3072]
    const float* thr      = (const float*)d_in[2];  // [512][6]
    const float* ltemp    = (const float*)d_in[3];  // [512][6]
    const float* response = (const float*)d_in[4];  // [512][3][64]
    float* out = (float*)d_out;                     // [512][1536]

    cudaFuncSetAttribute(gemm_hmma_kernel,
                         cudaFuncAttributeMaxDynamicSharedMemorySize, SM_TOTAL);

    prep_kernel<<<ENT_BLOCKS + SPL_BLOCKS, 128>>>(fa, input);

    dim3 g2(NCOLS / 128, BATCH / 64);
    gemm_hmma_kernel<<<g2, 256, SM_TOTAL>>>(thr, ltemp);

    dim3 g3(NTREES / TT, BATCH / BB);
    leaf_kernel<<<g3, 256>>>(response, out);
}

// round 13
// speedup vs baseline: 1.0121x; 1.0022x over previous
#include <cuda_runtime.h>
#include <cuda_bf16.h>
#include <math.h>
#include <stdint.h>

// Problem constants
#define F_IN   256
#define NTREES 512
#define DEPTH  6
#define TDIM   3
#define BATCH  512
#define NCOLS  (NTREES * DEPTH)   // 3072
#define KS     512                // stored K: [hi || lo]
#define KV     768                // virtual K in GEMM: hi.hi + lo.hi + hi.lo

// Scratch (device globals)
__device__ __nv_bfloat16 g_A[NCOLS * KS];   // W^T: [n][k]=hi, [n][256+k]=lo
__device__ __nv_bfloat16 g_B[BATCH * KS];   // in : [b][k]=hi, [b][256+k]=lo
__device__ float g_tl[NCOLS * BATCH];       // thresholded logits [3072][512]

// ---------------------------------------------------------------------------
// Portable tensor-path helpers (sm_80+ baseline; ptxas targets plain sm_103)
// ---------------------------------------------------------------------------
__device__ __forceinline__ uint32_t smem_u32(const void* p) {
    uint32_t a;
    asm("{ .reg .u64 t; cvta.to.shared.u64 t, %1; cvt.u32.u64 %0, t; }" : "=r"(a) : "l"(p));
    return a;
}
__device__ __forceinline__ void cpa16(uint32_t dst, const void* src) {
    asm volatile("cp.async.cg.shared.global [%0], [%1], 16;" :: "r"(dst), "l"(src));
}
__device__ __forceinline__ void ldsm4(uint32_t* r, uint32_t addr) {
    asm volatile("ldmatrix.sync.aligned.m8n8.x4.shared.b16 {%0,%1,%2,%3}, [%4];"
                 : "=r"(r[0]), "=r"(r[1]), "=r"(r[2]), "=r"(r[3]) : "r"(addr));
}
__device__ __forceinline__ void mma16816(float* c, const uint32_t* a,
                                         uint32_t b0, uint32_t b1) {
    asm volatile(
        "mma.sync.aligned.m16n8k16.row.col.f32.bf16.bf16.f32 "
        "{%0,%1,%2,%3}, {%4,%5,%6,%7}, {%8,%9}, {%0,%1,%2,%3};"
        : "+f"(c[0]), "+f"(c[1]), "+f"(c[2]), "+f"(c[3])
        : "r"(a[0]), "r"(a[1]), "r"(a[2]), "r"(a[3]), "r"(b0), "r"(b1));
}
// 128B-row XOR swizzle: 16B chunk index ^= (row & 7)
__device__ __forceinline__ uint32_t swz(uint32_t base, int row, int kbyte) {
    uint32_t off = (uint32_t)(row * 128 + kbyte);
    return base + (off ^ ((off >> 3) & 0x70));
}

// ---------------------------------------------------------------------------
// Kernel 1: fused prep.
// Blocks [0, 768): exact 1.5-entmax, one warp per column -> g_A [hi || lo].
//   Newton on g(tau)=sum relu(z-tau)^2-1 (convex => monotone from tau0=-1).
//   Lane owns k in [8*lane, 8*lane+8). 9 iterations (12/14/16 verified
//   bit-identical; Newton is support-discovery + quadratic polish and
//   converges well before 12).
// Blocks [768, 1024): split input fp32 -> g_B [hi || lo].
// ---------------------------------------------------------------------------
#define CPB 4
#define ENT_BLOCKS (NCOLS / CPB)          // 768
#define SPL_BLOCKS (BATCH * F_IN / 512)   // 256

__global__ void __launch_bounds__(128, 8)
prep_kernel(const float* __restrict__ fa,
            const float* __restrict__ input)
{
    const int tid = threadIdx.x;

    if (blockIdx.x >= ENT_BLOCKS) {
        // ---- split input: [hi || lo] rows of g_B ----
        int i = (blockIdx.x - ENT_BLOCKS) * 128 + tid;  // float4 units
        int b = i >> 6;
        int r = i & 63;                                  // k = 4*r
        float4 v = ((const float4*)input)[i];
        __nv_bfloat162 h01 = __float22bfloat162_rn(make_float2(v.x, v.y));
        __nv_bfloat162 h23 = __float22bfloat162_rn(make_float2(v.z, v.w));
        __nv_bfloat162 l01 = __float22bfloat162_rn(make_float2(
            v.x - __bfloat162float(h01.x), v.y - __bfloat162float(h01.y)));
        __nv_bfloat162 l23 = __float22bfloat162_rn(make_float2(
            v.z - __bfloat162float(h23.x), v.w - __bfloat162float(h23.y)));
        __nv_bfloat16* rowp = g_B + b * KS + r * 4;
        *(uint2*)rowp         = make_uint2(*(uint32_t*)&h01, *(uint32_t*)&h23);
        *(uint2*)(rowp + 256) = make_uint2(*(uint32_t*)&l01, *(uint32_t*)&l23);
        return;
    }

    // ---- entmax: warp per column ----
    __shared__ float s[CPB][260];

    const int c0   = blockIdx.x * CPB;
    const int lane = tid & 31;
    const int w    = tid >> 5;       // column within block

    #pragma unroll
    for (int i = 0; i < 8; i++) {
        int e = tid + i * 128;
        int c = e & 3;
        int r = e >> 2;
        s[c][r] = 0.5f * fa[r * NCOLS + c0 + c];
    }
    __syncthreads();

    // lane owns k = 8*lane .. 8*lane+7
    float4 za = *(const float4*)&s[w][lane * 8];
    float4 zb = *(const float4*)&s[w][lane * 8 + 4];

    // column max
    float mx = fmaxf(fmaxf(fmaxf(za.x, za.y), fmaxf(za.z, za.w)),
                     fmaxf(fmaxf(zb.x, zb.y), fmaxf(zb.z, zb.w)));
    #pragma unroll
    for (int off = 16; off > 0; off >>= 1)
        mx = fmaxf(mx, __shfl_xor_sync(0xffffffffu, mx, off));
    za.x -= mx; za.y -= mx; za.z -= mx; za.w -= mx;
    zb.x -= mx; zb.y -= mx; zb.z -= mx; zb.w -= mx;

    // Newton: tau0 = -1 (max(z)=0); monotone from below; fast division.
    float tau = -1.0f;
    for (int it = 0; it < 9; it++) {
        float d0 = fmaxf(za.x - tau, 0.0f);
        float d1 = fmaxf(za.y - tau, 0.0f);
        float d2 = fmaxf(za.z - tau, 0.0f);
        float d3 = fmaxf(za.w - tau, 0.0f);
        float d4 = fmaxf(zb.x - tau, 0.0f);
        float d5 = fmaxf(zb.y - tau, 0.0f);
        float d6 = fmaxf(zb.z - tau, 0.0f);
        float d7 = fmaxf(zb.w - tau, 0.0f);
        float s1 = ((d0 + d1) + (d2 + d3)) + ((d4 + d5) + (d6 + d7));
        float p0 = fmaf(d1, d1, d0 * d0);
        float p1 = fmaf(d3, d3, d2 * d2);
        float p2 = fmaf(d5, d5, d4 * d4);
        float p3 = fmaf(d7, d7, d6 * d6);
        float s2 = (p0 + p1) + (p2 + p3);
        #pragma unroll
        for (int off = 16; off > 0; off >>= 1) {
            s1 += __shfl_xor_sync(0xffffffffu, s1, off);
            s2 += __shfl_xor_sync(0xffffffffu, s2, off);
        }
        tau += __fdividef(s2 - 1.0f, 2.0f * s1);
    }

    // emit [hi || lo]: 8 bf16 = 16B per segment -> 2x STG.128, coalesced
    float d0 = fmaxf(za.x - tau, 0.0f);
    float d1 = fmaxf(za.y - tau, 0.0f);
    float d2 = fmaxf(za.z - tau, 0.0f);
    float d3 = fmaxf(za.w - tau, 0.0f);
    float d4 = fmaxf(zb.x - tau, 0.0f);
    float d5 = fmaxf(zb.y - tau, 0.0f);
    float d6 = fmaxf(zb.z - tau, 0.0f);
    float d7 = fmaxf(zb.w - tau, 0.0f);
    float w0 = d0*d0, w1 = d1*d1, w2 = d2*d2, w3 = d3*d3;
    float w4 = d4*d4, w5 = d5*d5, w6 = d6*d6, w7 = d7*d7;

    __nv_bfloat162 h01 = __float22bfloat162_rn(make_float2(w0, w1));
    __nv_bfloat162 h23 = __float22bfloat162_rn(make_float2(w2, w3));
    __nv_bfloat162 h45 = __float22bfloat162_rn(make_float2(w4, w5));
    __nv_bfloat162 h67 = __float22bfloat162_rn(make_float2(w6, w7));
    __nv_bfloat162 l01 = __float22bfloat162_rn(make_float2(
        w0 - __bfloat162float(h01.x), w1 - __bfloat162float(h01.y)));
    __nv_bfloat162 l23 = __float22bfloat162_rn(make_float2(
        w2 - __bfloat162float(h23.x), w3 - __bfloat162float(h23.y)));
    __nv_bfloat162 l45 = __float22bfloat162_rn(make_float2(
        w4 - __bfloat162float(h45.x), w5 - __bfloat162float(h45.y)));
    __nv_bfloat162 l67 = __float22bfloat162_rn(make_float2(
        w6 - __bfloat162float(h67.x), w7 - __bfloat162float(h67.y)));

    __nv_bfloat16* Arow = g_A + (size_t)(c0 + w) * KS;
    uint4 hv = make_uint4(*(uint32_t*)&h01, *(uint32_t*)&h23,
                          *(uint32_t*)&h45, *(uint32_t*)&h67);
    uint4 lv = make_uint4(*(uint32_t*)&l01, *(uint32_t*)&l23,
                          *(uint32_t*)&l45, *(uint32_t*)&l67);
    *(uint4*)(Arow + lane * 8)       = hv;
    *(uint4*)(Arow + 256 + lane * 8) = lv;
}

// ---------------------------------------------------------------------------
// Kernel 2: HMMA bf16 GEMM over virtual K=768:
//   kc 0-3:  A hi x B hi;  kc 4-7: A lo x B hi;  kc 8-11: A hi x B lo
// (drops only loA.loB ~ 2^-18). Stored arrays are [hi||lo], 512 wide.
// ---------------------------------------------------------------------------
#define CK 64
#define NKC (KV / CK)    // 12

#define SA0 0
#define SA1 16384
#define SB0 32768
#define SB1 40960
#define SM_TOTAL 49152

__device__ __forceinline__ int map_kcA(int kc) { return kc < 8 ? kc : kc - 8; }
__device__ __forceinline__ int map_kcB(int kc) { return kc < 4 ? kc : kc - 4; }

__device__ __forceinline__ void load_A_chunk(uint32_t sbase, int n0, int kcA, int tid)
{
    #pragma unroll
    for (int j = 0; j < 4; j++) {
        int e = tid + j * 256;
        int row = e >> 3;
        int ch  = e & 7;
        cpa16(swz(sbase, row, ch * 16),
              g_A + (size_t)(n0 + row) * KS + kcA * CK + ch * 8);
    }
}
__device__ __forceinline__ void load_B_chunk(uint32_t sbase, int b0, int kcB, int tid)
{
    #pragma unroll
    for (int j = 0; j < 2; j++) {
        int e = tid + j * 256;
        int row = e >> 3;
        int ch  = e & 7;
        cpa16(swz(sbase, row, ch * 16),
              g_B + (size_t)(b0 + row) * KS + kcB * CK + ch * 8);
    }
}

__global__ void __launch_bounds__(256, 2)
gemm_hmma_kernel(const float* __restrict__ thr,
                 const float* __restrict__ ltemp)
{
    extern __shared__ char smem[];
    const uint32_t sb = smem_u32(smem);
    const int tid  = threadIdx.x;
    const int lane = tid & 31;
    const int wid  = tid >> 5;
    const int wm   = wid >> 1;
    const int wn   = wid & 1;

    const int n0 = blockIdx.x * 128;
    const int b0 = blockIdx.y * 64;

    const uint32_t sA[2] = {sb + SA0, sb + SA1};
    const uint32_t sB[2] = {sb + SB0, sb + SB1};

    float acc[2][4][4];
    #pragma unroll
    for (int mi = 0; mi < 2; mi++)
        #pragma unroll
        for (int ni = 0; ni < 4; ni++)
            #pragma unroll
            for (int q = 0; q < 4; q++) acc[mi][ni][q] = 0.0f;

    load_A_chunk(sA[0], n0, map_kcA(0), tid);
    load_B_chunk(sB[0], b0, map_kcB(0), tid);
    asm volatile("cp.async.commit_group;");

    const int lane15 = lane & 15;
    const int khalf  = (lane >> 4) * 16;

    int buf = 0;
    for (int kc = 0; kc < NKC; kc++) {
        if (kc + 1 < NKC) {
            load_A_chunk(sA[buf ^ 1], n0, map_kcA(kc + 1), tid);
            load_B_chunk(sB[buf ^ 1], b0, map_kcB(kc + 1), tid);
            asm volatile("cp.async.commit_group;");
            asm volatile("cp.async.wait_group 1;");
        } else {
            asm volatile("cp.async.wait_group 0;");
        }
        __syncthreads();

        #pragma unroll
        for (int ks = 0; ks < 4; ks++) {
            const int kbyte = ks * 32 + khalf;
            uint32_t a0[4], a1[4], bq0[4], bq1[4];
            ldsm4(a0,  swz(sA[buf], wm * 32 + lane15,      kbyte));
            ldsm4(a1,  swz(sA[buf], wm * 32 + 16 + lane15, kbyte));
            ldsm4(bq0, swz(sB[buf], wn * 32 + lane15,      kbyte));
            ldsm4(bq1, swz(sB[buf], wn * 32 + 16 + lane15, kbyte));

            mma16816(acc[0][0], a0, bq0[0], bq0[2]);
            mma16816(acc[0][1], a0, bq0[1], bq0[3]);
            mma16816(acc[0][2], a0, bq1[0], bq1[2]);
            mma16816(acc[0][3], a0, bq1[1], bq1[3]);
            mma16816(acc[1][0], a1, bq0[0], bq0[2]);
            mma16816(acc[1][1], a1, bq0[1], bq0[3]);
            mma16816(acc[1][2], a1, bq1[0], bq1[2]);
            mma16816(acc[1][3], a1, bq1[1], bq1[3]);
        }
        __syncthreads();
        buf ^= 1;
    }

    const int qr = lane >> 2;
    const int qc = (lane & 3) * 2;
    #pragma unroll
    for (int mi = 0; mi < 2; mi++) {
        const int nr0 = n0 + wm * 32 + mi * 16 + qr;
        const int nr1 = nr0 + 8;
        const int t0 = nr0 / DEPTH, d0 = nr0 % DEPTH;
        const int t1 = nr1 / DEPTH, d1 = nr1 % DEPTH;
        const float th0 = thr[t0 * DEPTH + d0];
        const float sc0 = expf(-ltemp[t0 * DEPTH + d0]);
        const float th1 = thr[t1 * DEPTH + d1];
        const float sc1 = expf(-ltemp[t1 * DEPTH + d1]);
        #pragma unroll
        for (int ni = 0; ni < 4; ni++) {
            const int bc = b0 + wn * 32 + ni * 8 + qc;
            float2 v0, v1;
            v0.x = (acc[mi][ni][0] - th0) * sc0;
            v0.y = (acc[mi][ni][1] - th0) * sc0;
            v1.x = (acc[mi][ni][2] - th1) * sc1;
            v1.y = (acc[mi][ni][3] - th1) * sc1;
            *(float2*)&g_tl[(size_t)nr0 * BATCH + bc] = v0;
            *(float2*)&g_tl[(size_t)nr1 * BATCH + bc] = v1;
        }
    }
}

// ---------------------------------------------------------------------------
// Kernel 3: one (tree, batch) pair per thread. Block = 8 trees x 32 batches.
// ---------------------------------------------------------------------------
#define TT 8    // trees per block
#define BB 32   // batches per block

__global__ void __launch_bounds__(256, 4)
leaf_kernel(const float* __restrict__ response,  // [512][3][64]
            float* __restrict__ out)             // [512][1536]
{
    __shared__ float4 rsp4[TT * 48];
    __shared__ float  sout[BB][TT * 3 + 3];

    const int t0   = blockIdx.x * TT;
    const int b0   = blockIdx.y * BB;
    const int tid  = threadIdx.x;
    const int lane = tid & 31;
    const int w    = tid >> 5;

    for (int i = tid; i < TT * 48; i += 256)
        rsp4[i] = ((const float4*)response)[(size_t)t0 * 48 + i];
    __syncthreads();

    const int t = t0 + w;
    const int b = b0 + lane;

    float a[DEPTH], bb[DEPTH];
    #pragma unroll
    for (int d = 0; d < DEPTH; d++) {
        float v = g_tl[(size_t)(t * DEPTH + d) * BATCH + b];
        float x = 0.5f * v;
        a[d]  = fminf(fmaxf(0.5f + x, -0.5f), 1.5f);
        bb[d] = fminf(fmaxf(0.5f - x, -0.5f), 1.5f);
    }

    float w8[8];
    w8[0] = 1.0f;
    #pragma unroll
    for (int d = 0; d < 3; d++) {
        const int sz = 1 << d;
        #pragma unroll
        for (int i = sz - 1; i >= 0; i--) {
            w8[i + sz] = w8[i] * bb[d];
            w8[i]      = w8[i] * a[d];
        }
    }
    float q8[8];
    q8[0] = 1.0f;
    #pragma unroll
    for (int e = 0; e < 3; e++) {
        const int sz = 1 << e;
        #pragma unroll
        for (int i = sz - 1; i >= 0; i--) {
            q8[i + sz] = q8[i] * bb[3 + e];
            q8[i]      = q8[i] * a[3 + e];
        }
    }

    const float4* rp = &rsp4[w * 48];
    float o0 = 0.0f, o1 = 0.0f, o2 = 0.0f;
    #pragma unroll
    for (int j = 0; j < 8; j++) {
        float4 r00 = rp[j * 2],      r01 = rp[j * 2 + 1];
        float4 r10 = rp[16 + j * 2], r11 = rp[16 + j * 2 + 1];
        float4 r20 = rp[32 + j * 2], r21 = rp[32 + j * 2 + 1];
        float s0 = w8[0]*r00.x + w8[1]*r00.y + w8[2]*r00.z + w8[3]*r00.w
                 + w8[4]*r01.x + w8[5]*r01.y + w8[6]*r01.z + w8[7]*r01.w;
        float s1 = w8[0]*r10.x + w8[1]*r10.y + w8[2]*r10.z + w8[3]*r10.w
                 + w8[4]*r11.x + w8[5]*r11.y + w8[6]*r11.z + w8[7]*r11.w;
        float s2 = w8[0]*r20.x + w8[1]*r20.y + w8[2]*r20.z + w8[3]*r20.w
                 + w8[4]*r21.x + w8[5]*r21.y + w8[6]*r21.z + w8[7]*r21.w;
        o0 = fmaf(q8[j], s0, o0);
        o1 = fmaf(q8[j], s1, o1);
        o2 = fmaf(q8[j], s2, o2);
    }

    sout[lane][w * 3 + 0] = o0;
    sout[lane][w * 3 + 1] = o1;
    sout[lane][w * 3 + 2] = o2;
    __syncthreads();

    if (tid < (BB * TT * 3) / 4) {
        int row = tid / 6;
        int col = tid % 6;
        float4 v;
        v.x = sout[row][col * 4 + 0];
        v.y = sout[row][col * 4 + 1];
        v.z = sout[row][col * 4 + 2];
        v.w = sout[row][col * 4 + 3];
        *(float4*)&out[(size_t)(b0 + row) * (NTREES * TDIM) + t0 * 3 + col * 4] = v;
    }
}

// ---------------------------------------------------------------------------
extern "C" void kernel_launch(void* const* d_in, const int* in_sizes, int n_in,
                              void* d_out, int out_size)
{
    const float* input    = (const float*)d_in[0];  // [512][256]
    const float* fa       = (const float*)d_in[1];  // [256][3072]
    const float* thr      = (const float*)d_in[2];  // [512][6]
    const float* ltemp    = (const float*)d_in[3];  // [512][6]
    const float* response = (const float*)d_in[4];  // [512][3][64]
    float* out = (float*)d_out;                     // [512][1536]

    cudaFuncSetAttribute(gemm_hmma_kernel,
                         cudaFuncAttributeMaxDynamicSharedMemorySize, SM_TOTAL);

    prep_kernel<<<ENT_BLOCKS + SPL_BLOCKS, 128>>>(fa, input);

    dim3 g2(NCOLS / 128, BATCH / 64);
    gemm_hmma_kernel<<<g2, 256, SM_TOTAL>>>(thr, ltemp);

    dim3 g3(NTREES / TT, BATCH / BB);
    leaf_kernel<<<g3, 256>>>(response, out);
}

// round 14
// speedup vs baseline: 1.1631x; 1.1492x over previous
#include <cuda_runtime.h>
#include <cuda_fp16.h>
#include <math.h>
#include <stdint.h>

// Problem constants
#define F_IN   256
#define NTREES 512
#define DEPTH  6
#define TDIM   3
#define BATCH  512
#define NCOLS  (NTREES * DEPTH)   // 3072
#define KSA    512                // A stored K: [hi || lo]  (fp16)
#define KSB    256                // B stored K: hi only     (fp16)
#define KV     512                // virtual K in GEMM: hiA.hiB + loA.hiB

// Scratch (device globals)
__device__ __half g_A[NCOLS * KSA];   // W^T: [n][k]=hi, [n][256+k]=lo
__device__ __half g_B[BATCH * KSB];   // in : [b][k]=hi
__device__ float g_tl[NCOLS * BATCH]; // thresholded logits [3072][512]

// ---------------------------------------------------------------------------
// Portable tensor-path helpers (sm_80+ baseline; ptxas targets plain sm_103)
// ---------------------------------------------------------------------------
__device__ __forceinline__ uint32_t smem_u32(const void* p) {
    uint32_t a;
    asm("{ .reg .u64 t; cvta.to.shared.u64 t, %1; cvt.u32.u64 %0, t; }" : "=r"(a) : "l"(p));
    return a;
}
__device__ __forceinline__ void cpa16(uint32_t dst, const void* src) {
    asm volatile("cp.async.cg.shared.global [%0], [%1], 16;" :: "r"(dst), "l"(src));
}
__device__ __forceinline__ void ldsm4(uint32_t* r, uint32_t addr) {
    asm volatile("ldmatrix.sync.aligned.m8n8.x4.shared.b16 {%0,%1,%2,%3}, [%4];"
                 : "=r"(r[0]), "=r"(r[1]), "=r"(r[2]), "=r"(r[3]) : "r"(addr));
}
__device__ __forceinline__ void mma16816(float* c, const uint32_t* a,
                                         uint32_t b0, uint32_t b1) {
    asm volatile(
        "mma.sync.aligned.m16n8k16.row.col.f32.f16.f16.f32 "
        "{%0,%1,%2,%3}, {%4,%5,%6,%7}, {%8,%9}, {%0,%1,%2,%3};"
        : "+f"(c[0]), "+f"(c[1]), "+f"(c[2]), "+f"(c[3])
        : "r"(a[0]), "r"(a[1]), "r"(a[2]), "r"(a[3]), "r"(b0), "r"(b1));
}
// 128B-row XOR swizzle: 16B chunk index ^= (row & 7)
__device__ __forceinline__ uint32_t swz(uint32_t base, int row, int kbyte) {
    uint32_t off = (uint32_t)(row * 128 + kbyte);
    return base + (off ^ ((off >> 3) & 0x70));
}

// ---------------------------------------------------------------------------
// Kernel 1: fused prep.
// Blocks [0, 768): exact 1.5-entmax, one warp per column -> g_A [hi || lo] fp16.
//   Newton on g(tau)=sum relu(z-tau)^2-1 (convex => monotone from tau0=-1).
// Blocks [768, 1024): input fp32 -> fp16 hi into g_B.
// ---------------------------------------------------------------------------
#define CPB 4
#define ENT_BLOCKS (NCOLS / CPB)          // 768
#define SPL_BLOCKS (BATCH * F_IN / 512)   // 256

__global__ void __launch_bounds__(128, 8)
prep_kernel(const float* __restrict__ fa,
            const float* __restrict__ input)
{
    const int tid = threadIdx.x;

    if (blockIdx.x >= ENT_BLOCKS) {
        // ---- input -> fp16 hi rows of g_B ----
        int i = (blockIdx.x - ENT_BLOCKS) * 128 + tid;  // float4 units
        int b = i >> 6;
        int r = i & 63;                                  // k = 4*r
        float4 v = ((const float4*)input)[i];
        __half2 h01 = __float22half2_rn(make_float2(v.x, v.y));
        __half2 h23 = __float22half2_rn(make_float2(v.z, v.w));
        *(uint2*)(g_B + b * KSB + r * 4) =
            make_uint2(*(uint32_t*)&h01, *(uint32_t*)&h23);
        return;
    }

    // ---- entmax: warp per column ----
    __shared__ float s[CPB][260];

    const int c0   = blockIdx.x * CPB;
    const int lane = tid & 31;
    const int w    = tid >> 5;       // column within block

    #pragma unroll
    for (int i = 0; i < 8; i++) {
        int e = tid + i * 128;
        int c = e & 3;
        int r = e >> 2;
        s[c][r] = 0.5f * fa[r * NCOLS + c0 + c];
    }
    __syncthreads();

    // lane owns k = 8*lane .. 8*lane+7
    float4 za = *(const float4*)&s[w][lane * 8];
    float4 zb = *(const float4*)&s[w][lane * 8 + 4];

    // column max
    float mx = fmaxf(fmaxf(fmaxf(za.x, za.y), fmaxf(za.z, za.w)),
                     fmaxf(fmaxf(zb.x, zb.y), fmaxf(zb.z, zb.w)));
    #pragma unroll
    for (int off = 16; off > 0; off >>= 1)
        mx = fmaxf(mx, __shfl_xor_sync(0xffffffffu, mx, off));
    za.x -= mx; za.y -= mx; za.z -= mx; za.w -= mx;
    zb.x -= mx; zb.y -= mx; zb.z -= mx; zb.w -= mx;

    // Newton: tau0 = -1 (max(z)=0); monotone from below; fast division.
    float tau = -1.0f;
    for (int it = 0; it < 9; it++) {
        float d0 = fmaxf(za.x - tau, 0.0f);
        float d1 = fmaxf(za.y - tau, 0.0f);
        float d2 = fmaxf(za.z - tau, 0.0f);
        float d3 = fmaxf(za.w - tau, 0.0f);
        float d4 = fmaxf(zb.x - tau, 0.0f);
        float d5 = fmaxf(zb.y - tau, 0.0f);
        float d6 = fmaxf(zb.z - tau, 0.0f);
        float d7 = fmaxf(zb.w - tau, 0.0f);
        float s1 = ((d0 + d1) + (d2 + d3)) + ((d4 + d5) + (d6 + d7));
        float p0 = fmaf(d1, d1, d0 * d0);
        float p1 = fmaf(d3, d3, d2 * d2);
        float p2 = fmaf(d5, d5, d4 * d4);
        float p3 = fmaf(d7, d7, d6 * d6);
        float s2 = (p0 + p1) + (p2 + p3);
        #pragma unroll
        for (int off = 16; off > 0; off >>= 1) {
            s1 += __shfl_xor_sync(0xffffffffu, s1, off);
            s2 += __shfl_xor_sync(0xffffffffu, s2, off);
        }
        tau += __fdividef(s2 - 1.0f, 2.0f * s1);
    }

    // emit [hi || lo] fp16: 8 halfs = 16B per segment -> 2x STG.128
    float d0 = fmaxf(za.x - tau, 0.0f);
    float d1 = fmaxf(za.y - tau, 0.0f);
    float d2 = fmaxf(za.z - tau, 0.0f);
    float d3 = fmaxf(za.w - tau, 0.0f);
    float d4 = fmaxf(zb.x - tau, 0.0f);
    float d5 = fmaxf(zb.y - tau, 0.0f);
    float d6 = fmaxf(zb.z - tau, 0.0f);
    float d7 = fmaxf(zb.w - tau, 0.0f);
    float w0 = d0*d0, w1 = d1*d1, w2 = d2*d2, w3 = d3*d3;
    float w4 = d4*d4, w5 = d5*d5, w6 = d6*d6, w7 = d7*d7;

    __half2 h01 = __float22half2_rn(make_float2(w0, w1));
    __half2 h23 = __float22half2_rn(make_float2(w2, w3));
    __half2 h45 = __float22half2_rn(make_float2(w4, w5));
    __half2 h67 = __float22half2_rn(make_float2(w6, w7));
    __half2 l01 = __float22half2_rn(make_float2(
        w0 - __half2float(h01.x), w1 - __half2float(h01.y)));
    __half2 l23 = __float22half2_rn(make_float2(
        w2 - __half2float(h23.x), w3 - __half2float(h23.y)));
    __half2 l45 = __float22half2_rn(make_float2(
        w4 - __half2float(h45.x), w5 - __half2float(h45.y)));
    __half2 l67 = __float22half2_rn(make_float2(
        w6 - __half2float(h67.x), w7 - __half2float(h67.y)));

    __half* Arow = g_A + (size_t)(c0 + w) * KSA;
    uint4 hv = make_uint4(*(uint32_t*)&h01, *(uint32_t*)&h23,
                          *(uint32_t*)&h45, *(uint32_t*)&h67);
    uint4 lv = make_uint4(*(uint32_t*)&l01, *(uint32_t*)&l23,
                          *(uint32_t*)&l45, *(uint32_t*)&l67);
    *(uint4*)(Arow + lane * 8)       = hv;
    *(uint4*)(Arow + 256 + lane * 8) = lv;
}

// ---------------------------------------------------------------------------
// Kernel 2: HMMA fp16 GEMM over virtual K=512:
//   kc 0-3: A hi x B hi;  kc 4-7: A lo x B hi
// (drops hiA.loB ~ calibrated 7e-5 end-to-end; loA.loB negligible).
// CTA: M=128(n) x N=64(b), 8 warps, double-buffered cp.async, XOR swizzle.
// ---------------------------------------------------------------------------
#define CK 64
#define NKC (KV / CK)    // 8

#define SA0 0
#define SA1 16384
#define SB0 32768
#define SB1 40960
#define SM_TOTAL 49152

__device__ __forceinline__ void load_A_chunk(uint32_t sbase, int n0, int kcA, int tid)
{
    #pragma unroll
    for (int j = 0; j < 4; j++) {
        int e = tid + j * 256;
        int row = e >> 3;
        int ch  = e & 7;
        cpa16(swz(sbase, row, ch * 16),
              g_A + (size_t)(n0 + row) * KSA + kcA * CK + ch * 8);
    }
}
__device__ __forceinline__ void load_B_chunk(uint32_t sbase, int b0, int kcB, int tid)
{
    #pragma unroll
    for (int j = 0; j < 2; j++) {
        int e = tid + j * 256;
        int row = e >> 3;
        int ch  = e & 7;
        cpa16(swz(sbase, row, ch * 16),
              g_B + (size_t)(b0 + row) * KSB + kcB * CK + ch * 8);
    }
}

__global__ void __launch_bounds__(256, 2)
gemm_hmma_kernel(const float* __restrict__ thr,
                 const float* __restrict__ ltemp)
{
    extern __shared__ char smem[];
    const uint32_t sb = smem_u32(smem);
    const int tid  = threadIdx.x;
    const int lane = tid & 31;
    const int wid  = tid >> 5;
    const int wm   = wid >> 1;
    const int wn   = wid & 1;

    const int n0 = blockIdx.x * 128;
    const int b0 = blockIdx.y * 64;

    const uint32_t sA[2] = {sb + SA0, sb + SA1};
    const uint32_t sB[2] = {sb + SB0, sb + SB1};

    float acc[2][4][4];
    #pragma unroll
    for (int mi = 0; mi < 2; mi++)
        #pragma unroll
        for (int ni = 0; ni < 4; ni++)
            #pragma unroll
            for (int q = 0; q < 4; q++) acc[mi][ni][q] = 0.0f;

    load_A_chunk(sA[0], n0, 0, tid);
    load_B_chunk(sB[0], b0, 0, tid);
    asm volatile("cp.async.commit_group;");

    const int lane15 = lane & 15;
    const int khalf  = (lane >> 4) * 16;

    int buf = 0;
    for (int kc = 0; kc < NKC; kc++) {
        if (kc + 1 < NKC) {
            load_A_chunk(sA[buf ^ 1], n0, kc + 1, tid);
            load_B_chunk(sB[buf ^ 1], b0, (kc + 1) & 3, tid);
            asm volatile("cp.async.commit_group;");
            asm volatile("cp.async.wait_group 1;");
        } else {
            asm volatile("cp.async.wait_group 0;");
        }
        __syncthreads();

        #pragma unroll
        for (int ks = 0; ks < 4; ks++) {
            const int kbyte = ks * 32 + khalf;
            uint32_t a0[4], a1[4], bq0[4], bq1[4];
            ldsm4(a0,  swz(sA[buf], wm * 32 + lane15,      kbyte));
            ldsm4(a1,  swz(sA[buf], wm * 32 + 16 + lane15, kbyte));
            ldsm4(bq0, swz(sB[buf], wn * 32 + lane15,      kbyte));
            ldsm4(bq1, swz(sB[buf], wn * 32 + 16 + lane15, kbyte));

            mma16816(acc[0][0], a0, bq0[0], bq0[2]);
            mma16816(acc[0][1], a0, bq0[1], bq0[3]);
            mma16816(acc[0][2], a0, bq1[0], bq1[2]);
            mma16816(acc[0][3], a0, bq1[1], bq1[3]);
            mma16816(acc[1][0], a1, bq0[0], bq0[2]);
            mma16816(acc[1][1], a1, bq0[1], bq0[3]);
            mma16816(acc[1][2], a1, bq1[0], bq1[2]);
            mma16816(acc[1][3], a1, bq1[1], bq1[3]);
        }
        __syncthreads();
        buf ^= 1;
    }

    const int qr = lane >> 2;
    const int qc = (lane & 3) * 2;
    #pragma unroll
    for (int mi = 0; mi < 2; mi++) {
        const int nr0 = n0 + wm * 32 + mi * 16 + qr;
        const int nr1 = nr0 + 8;
        const int t0 = nr0 / DEPTH, d0 = nr0 % DEPTH;
        const int t1 = nr1 / DEPTH, d1 = nr1 % DEPTH;
        const float th0 = thr[t0 * DEPTH + d0];
        const float sc0 = expf(-ltemp[t0 * DEPTH + d0]);
        const float th1 = thr[t1 * DEPTH + d1];
        const float sc1 = expf(-ltemp[t1 * DEPTH + d1]);
        #pragma unroll
        for (int ni = 0; ni < 4; ni++) {
            const int bc = b0 + wn * 32 + ni * 8 + qc;
            float2 v0, v1;
            v0.x = (acc[mi][ni][0] - th0) * sc0;
            v0.y = (acc[mi][ni][1] - th0) * sc0;
            v1.x = (acc[mi][ni][2] - th1) * sc1;
            v1.y = (acc[mi][ni][3] - th1) * sc1;
            *(float2*)&g_tl[(size_t)nr0 * BATCH + bc] = v0;
            *(float2*)&g_tl[(size_t)nr1 * BATCH + bc] = v1;
        }
    }
}

// ---------------------------------------------------------------------------
// Kernel 3: one (tree, batch) pair per thread. Block = 8 trees x 32 batches.
// ---------------------------------------------------------------------------
#define TT 8    // trees per block
#define BB 32   // batches per block

__global__ void __launch_bounds__(256, 4)
leaf_kernel(const float* __restrict__ response,  // [512][3][64]
            float* __restrict__ out)             // [512][1536]
{
    __shared__ float4 rsp4[TT * 48];
    __shared__ float  sout[BB][TT * 3 + 3];

    const int t0   = blockIdx.x * TT;
    const int b0   = blockIdx.y * BB;
    const int tid  = threadIdx.x;
    const int lane = tid & 31;
    const int w    = tid >> 5;

    for (int i = tid; i < TT * 48; i += 256)
        rsp4[i] = ((const float4*)response)[(size_t)t0 * 48 + i];
    __syncthreads();

    const int t = t0 + w;
    const int b = b0 + lane;

    float a[DEPTH], bb[DEPTH];
    #pragma unroll
    for (int d = 0; d < DEPTH; d++) {
        float v = g_tl[(size_t)(t * DEPTH + d) * BATCH + b];
        float x = 0.5f * v;
        a[d]  = fminf(fmaxf(0.5f + x, -0.5f), 1.5f);
        bb[d] = fminf(fmaxf(0.5f - x, -0.5f), 1.5f);
    }

    float w8[8];
    w8[0] = 1.0f;
    #pragma unroll
    for (int d = 0; d < 3; d++) {
        const int sz = 1 << d;
        #pragma unroll
        for (int i = sz - 1; i >= 0; i--) {
            w8[i + sz] = w8[i] * bb[d];
            w8[i]      = w8[i] * a[d];
        }
    }
    float q8[8];
    q8[0] = 1.0f;
    #pragma unroll
    for (int e = 0; e < 3; e++) {
        const int sz = 1 << e;
        #pragma unroll
        for (int i = sz - 1; i >= 0; i--) {
            q8[i + sz] = q8[i] * bb[3 + e];
            q8[i]      = q8[i] * a[3 + e];
        }
    }

    const float4* rp = &rsp4[w * 48];
    float o0 = 0.0f, o1 = 0.0f, o2 = 0.0f;
    #pragma unroll
    for (int j = 0; j < 8; j++) {
        float4 r00 = rp[j * 2],      r01 = rp[j * 2 + 1];
        float4 r10 = rp[16 + j * 2], r11 = rp[16 + j * 2 + 1];
        float4 r20 = rp[32 + j * 2], r21 = rp[32 + j * 2 + 1];
        float s0 = w8[0]*r00.x + w8[1]*r00.y + w8[2]*r00.z + w8[3]*r00.w
                 + w8[4]*r01.x + w8[5]*r01.y + w8[6]*r01.z + w8[7]*r01.w;
        float s1 = w8[0]*r10.x + w8[1]*r10.y + w8[2]*r10.z + w8[3]*r10.w
                 + w8[4]*r11.x + w8[5]*r11.y + w8[6]*r11.z + w8[7]*r11.w;
        float s2 = w8[0]*r20.x + w8[1]*r20.y + w8[2]*r20.z + w8[3]*r20.w
                 + w8[4]*r21.x + w8[5]*r21.y + w8[6]*r21.z + w8[7]*r21.w;
        o0 = fmaf(q8[j], s0, o0);
        o1 = fmaf(q8[j], s1, o1);
        o2 = fmaf(q8[j], s2, o2);
    }

    sout[lane][w * 3 + 0] = o0;
    sout[lane][w * 3 + 1] = o1;
    sout[lane][w * 3 + 2] = o2;
    __syncthreads();

    if (tid < (BB * TT * 3) / 4) {
        int row = tid / 6;
        int col = tid % 6;
        float4 v;
        v.x = sout[row][col * 4 + 0];
        v.y = sout[row][col * 4 + 1];
        v.z = sout[row][col * 4 + 2];
        v.w = sout[row][col * 4 + 3];
        *(float4*)&out[(size_t)(b0 + row) * (NTREES * TDIM) + t0 * 3 + col * 4] = v;
    }
}

// ---------------------------------------------------------------------------
extern "C" void kernel_launch(void* const* d_in, const int* in_sizes, int n_in,
                              void* d_out, int out_size)
{
    const float* input    = (const float*)d_in[0];  // [512][256]
    const float* fa       = (const float*)d_in[1];  // [256][3072]
    const float* thr      = (const float*)d_in[2];  // [512][6]
    const float* ltemp    = (const float*)d_in[3];  // [512][6]
    const float* response = (const float*)d_in[4];  // [512][3][64]
    float* out = (float*)d_out;                     // [512][1536]

    cudaFuncSetAttribute(gemm_hmma_kernel,
                         cudaFuncAttributeMaxDynamicSharedMemorySize, SM_TOTAL);

    prep_kernel<<<ENT_BLOCKS + SPL_BLOCKS, 128>>>(fa, input);

    dim3 g2(NCOLS / 128, BATCH / 64);
    gemm_hmma_kernel<<<g2, 256, SM_TOTAL>>>(thr, ltemp);

    dim3 g3(NTREES / TT, BATCH / BB);
    leaf_kernel<<<g3, 256>>>(response, out);
}

// round 15
// speedup vs baseline: 1.4024x; 1.2058x over previous
#include <cuda_runtime.h>
#include <cuda_fp16.h>
#include <math.h>
#include <stdint.h>

// Problem constants
#define F_IN   256
#define NTREES 512
#define DEPTH  6
#define TDIM   3
#define BATCH  512
#define NCOLS  (NTREES * DEPTH)   // 3072
#define KSA    256                // A stored K (fp16 hi only)
#define KSB    256                // B stored K (fp16 hi only)
#define KV     256                // GEMM K: pure fp16 (calibrated ~1.2e-4 end-to-end)

// Scratch (device globals)
__device__ __half g_A[NCOLS * KSA];   // W^T fp16
__device__ __half g_B[BATCH * KSB];   // input fp16
__device__ float g_tl[NCOLS * BATCH]; // thresholded logits [3072][512]

// ---------------------------------------------------------------------------
// Portable tensor-path helpers (sm_80+ baseline; ptxas targets plain sm_103)
// ---------------------------------------------------------------------------
__device__ __forceinline__ uint32_t smem_u32(const void* p) {
    uint32_t a;
    asm("{ .reg .u64 t; cvta.to.shared.u64 t, %1; cvt.u32.u64 %0, t; }" : "=r"(a) : "l"(p));
    return a;
}
__device__ __forceinline__ void cpa16(uint32_t dst, const void* src) {
    asm volatile("cp.async.cg.shared.global [%0], [%1], 16;" :: "r"(dst), "l"(src));
}
__device__ __forceinline__ void ldsm4(uint32_t* r, uint32_t addr) {
    asm volatile("ldmatrix.sync.aligned.m8n8.x4.shared.b16 {%0,%1,%2,%3}, [%4];"
                 : "=r"(r[0]), "=r"(r[1]), "=r"(r[2]), "=r"(r[3]) : "r"(addr));
}
__device__ __forceinline__ void mma16816(float* c, const uint32_t* a,
                                         uint32_t b0, uint32_t b1) {
    asm volatile(
        "mma.sync.aligned.m16n8k16.row.col.f32.f16.f16.f32 "
        "{%0,%1,%2,%3}, {%4,%5,%6,%7}, {%8,%9}, {%0,%1,%2,%3};"
        : "+f"(c[0]), "+f"(c[1]), "+f"(c[2]), "+f"(c[3])
        : "r"(a[0]), "r"(a[1]), "r"(a[2]), "r"(a[3]), "r"(b0), "r"(b1));
}
// 128B-row XOR swizzle: 16B chunk index ^= (row & 7)
__device__ __forceinline__ uint32_t swz(uint32_t base, int row, int kbyte) {
    uint32_t off = (uint32_t)(row * 128 + kbyte);
    return base + (off ^ ((off >> 3) & 0x70));
}

// ---------------------------------------------------------------------------
// Kernel 1: fused prep.
// Blocks [0, 768): exact 1.5-entmax, one warp per column -> g_A fp16.
//   Newton on g(tau)=sum relu(z-tau)^2-1 (convex => monotone from tau0=-1).
// Blocks [768, 1024): input fp32 -> fp16 into g_B.
// ---------------------------------------------------------------------------
#define CPB 4
#define ENT_BLOCKS (NCOLS / CPB)          // 768
#define SPL_BLOCKS (BATCH * F_IN / 512)   // 256

__global__ void __launch_bounds__(128, 8)
prep_kernel(const float* __restrict__ fa,
            const float* __restrict__ input)
{
    const int tid = threadIdx.x;

    if (blockIdx.x >= ENT_BLOCKS) {
        // ---- input -> fp16 rows of g_B ----
        int i = (blockIdx.x - ENT_BLOCKS) * 128 + tid;  // float4 units
        int b = i >> 6;
        int r = i & 63;                                  // k = 4*r
        float4 v = ((const float4*)input)[i];
        __half2 h01 = __float22half2_rn(make_float2(v.x, v.y));
        __half2 h23 = __float22half2_rn(make_float2(v.z, v.w));
        *(uint2*)(g_B + b * KSB + r * 4) =
            make_uint2(*(uint32_t*)&h01, *(uint32_t*)&h23);
        return;
    }

    // ---- entmax: warp per column ----
    __shared__ float s[CPB][260];

    const int c0   = blockIdx.x * CPB;
    const int lane = tid & 31;
    const int w    = tid >> 5;       // column within block

    #pragma unroll
    for (int i = 0; i < 8; i++) {
        int e = tid + i * 128;
        int c = e & 3;
        int r = e >> 2;
        s[c][r] = 0.5f * fa[r * NCOLS + c0 + c];
    }
    __syncthreads();

    // lane owns k = 8*lane .. 8*lane+7
    float4 za = *(const float4*)&s[w][lane * 8];
    float4 zb = *(const float4*)&s[w][lane * 8 + 4];

    // column max
    float mx = fmaxf(fmaxf(fmaxf(za.x, za.y), fmaxf(za.z, za.w)),
                     fmaxf(fmaxf(zb.x, zb.y), fmaxf(zb.z, zb.w)));
    #pragma unroll
    for (int off = 16; off > 0; off >>= 1)
        mx = fmaxf(mx, __shfl_xor_sync(0xffffffffu, mx, off));
    za.x -= mx; za.y -= mx; za.z -= mx; za.w -= mx;
    zb.x -= mx; zb.y -= mx; zb.z -= mx; zb.w -= mx;

    // Newton: tau0 = -1 (max(z)=0); monotone from below; fast division.
    float tau = -1.0f;
    for (int it = 0; it < 9; it++) {
        float d0 = fmaxf(za.x - tau, 0.0f);
        float d1 = fmaxf(za.y - tau, 0.0f);
        float d2 = fmaxf(za.z - tau, 0.0f);
        float d3 = fmaxf(za.w - tau, 0.0f);
        float d4 = fmaxf(zb.x - tau, 0.0f);
        float d5 = fmaxf(zb.y - tau, 0.0f);
        float d6 = fmaxf(zb.z - tau, 0.0f);
        float d7 = fmaxf(zb.w - tau, 0.0f);
        float s1 = ((d0 + d1) + (d2 + d3)) + ((d4 + d5) + (d6 + d7));
        float p0 = fmaf(d1, d1, d0 * d0);
        float p1 = fmaf(d3, d3, d2 * d2);
        float p2 = fmaf(d5, d5, d4 * d4);
        float p3 = fmaf(d7, d7, d6 * d6);
        float s2 = (p0 + p1) + (p2 + p3);
        #pragma unroll
        for (int off = 16; off > 0; off >>= 1) {
            s1 += __shfl_xor_sync(0xffffffffu, s1, off);
            s2 += __shfl_xor_sync(0xffffffffu, s2, off);
        }
        tau += __fdividef(s2 - 1.0f, 2.0f * s1);
    }

    // emit fp16 weights: 8 halfs = 16B -> STG.128, coalesced
    float d0 = fmaxf(za.x - tau, 0.0f);
    float d1 = fmaxf(za.y - tau, 0.0f);
    float d2 = fmaxf(za.z - tau, 0.0f);
    float d3 = fmaxf(za.w - tau, 0.0f);
    float d4 = fmaxf(zb.x - tau, 0.0f);
    float d5 = fmaxf(zb.y - tau, 0.0f);
    float d6 = fmaxf(zb.z - tau, 0.0f);
    float d7 = fmaxf(zb.w - tau, 0.0f);

    __half2 h01 = __float22half2_rn(make_float2(d0 * d0, d1 * d1));
    __half2 h23 = __float22half2_rn(make_float2(d2 * d2, d3 * d3));
    __half2 h45 = __float22half2_rn(make_float2(d4 * d4, d5 * d5));
    __half2 h67 = __float22half2_rn(make_float2(d6 * d6, d7 * d7));

    __half* Arow = g_A + (size_t)(c0 + w) * KSA;
    *(uint4*)(Arow + lane * 8) =
        make_uint4(*(uint32_t*)&h01, *(uint32_t*)&h23,
                   *(uint32_t*)&h45, *(uint32_t*)&h67);
}

// ---------------------------------------------------------------------------
// Kernel 2: HMMA fp16 GEMM, K=256 (pure fp16; calibrated rel_err ~1.2e-4).
// CTA: M=128(n) x N=64(b), 8 warps of 32x32, K chunks of 64, double-buffered
// cp.async, XOR-swizzled smem, ldmatrix.x4, fused threshold epilogue.
// ---------------------------------------------------------------------------
#define CK 64
#define NKC (KV / CK)    // 4

#define SA0 0
#define SA1 16384
#define SB0 32768
#define SB1 40960
#define SM_TOTAL 49152

__device__ __forceinline__ void load_A_chunk(uint32_t sbase, int n0, int kc, int tid)
{
    #pragma unroll
    for (int j = 0; j < 4; j++) {
        int e = tid + j * 256;
        int row = e >> 3;
        int ch  = e & 7;
        cpa16(swz(sbase, row, ch * 16),
              g_A + (size_t)(n0 + row) * KSA + kc * CK + ch * 8);
    }
}
__device__ __forceinline__ void load_B_chunk(uint32_t sbase, int b0, int kc, int tid)
{
    #pragma unroll
    for (int j = 0; j < 2; j++) {
        int e = tid + j * 256;
        int row = e >> 3;
        int ch  = e & 7;
        cpa16(swz(sbase, row, ch * 16),
              g_B + (size_t)(b0 + row) * KSB + kc * CK + ch * 8);
    }
}

__global__ void __launch_bounds__(256, 2)
gemm_hmma_kernel(const float* __restrict__ thr,
                 const float* __restrict__ ltemp)
{
    extern __shared__ char smem[];
    const uint32_t sb = smem_u32(smem);
    const int tid  = threadIdx.x;
    const int lane = tid & 31;
    const int wid  = tid >> 5;
    const int wm   = wid >> 1;
    const int wn   = wid & 1;

    const int n0 = blockIdx.x * 128;
    const int b0 = blockIdx.y * 64;

    const uint32_t sA[2] = {sb + SA0, sb + SA1};
    const uint32_t sB[2] = {sb + SB0, sb + SB1};

    float acc[2][4][4];
    #pragma unroll
    for (int mi = 0; mi < 2; mi++)
        #pragma unroll
        for (int ni = 0; ni < 4; ni++)
            #pragma unroll
            for (int q = 0; q < 4; q++) acc[mi][ni][q] = 0.0f;

    load_A_chunk(sA[0], n0, 0, tid);
    load_B_chunk(sB[0], b0, 0, tid);
    asm volatile("cp.async.commit_group;");

    const int lane15 = lane & 15;
    const int khalf  = (lane >> 4) * 16;

    int buf = 0;
    for (int kc = 0; kc < NKC; kc++) {
        if (kc + 1 < NKC) {
            load_A_chunk(sA[buf ^ 1], n0, kc + 1, tid);
            load_B_chunk(sB[buf ^ 1], b0, kc + 1, tid);
            asm volatile("cp.async.commit_group;");
            asm volatile("cp.async.wait_group 1;");
        } else {
            asm volatile("cp.async.wait_group 0;");
        }
        __syncthreads();

        #pragma unroll
        for (int ks = 0; ks < 4; ks++) {
            const int kbyte = ks * 32 + khalf;
            uint32_t a0[4], a1[4], bq0[4], bq1[4];
            ldsm4(a0,  swz(sA[buf], wm * 32 + lane15,      kbyte));
            ldsm4(a1,  swz(sA[buf], wm * 32 + 16 + lane15, kbyte));
            ldsm4(bq0, swz(sB[buf], wn * 32 + lane15,      kbyte));
            ldsm4(bq1, swz(sB[buf], wn * 32 + 16 + lane15, kbyte));

            mma16816(acc[0][0], a0, bq0[0], bq0[2]);
            mma16816(acc[0][1], a0, bq0[1], bq0[3]);
            mma16816(acc[0][2], a0, bq1[0], bq1[2]);
            mma16816(acc[0][3], a0, bq1[1], bq1[3]);
            mma16816(acc[1][0], a1, bq0[0], bq0[2]);
            mma16816(acc[1][1], a1, bq0[1], bq0[3]);
            mma16816(acc[1][2], a1, bq1[0], bq1[2]);
            mma16816(acc[1][3], a1, bq1[1], bq1[3]);
        }
        __syncthreads();
        buf ^= 1;
    }

    const int qr = lane >> 2;
    const int qc = (lane & 3) * 2;
    #pragma unroll
    for (int mi = 0; mi < 2; mi++) {
        const int nr0 = n0 + wm * 32 + mi * 16 + qr;
        const int nr1 = nr0 + 8;
        const int t0 = nr0 / DEPTH, d0 = nr0 % DEPTH;
        const int t1 = nr1 / DEPTH, d1 = nr1 % DEPTH;
        const float th0 = thr[t0 * DEPTH + d0];
        const float sc0 = expf(-ltemp[t0 * DEPTH + d0]);
        const float th1 = thr[t1 * DEPTH + d1];
        const float sc1 = expf(-ltemp[t1 * DEPTH + d1]);
        #pragma unroll
        for (int ni = 0; ni < 4; ni++) {
            const int bc = b0 + wn * 32 + ni * 8 + qc;
            float2 v0, v1;
            v0.x = (acc[mi][ni][0] - th0) * sc0;
            v0.y = (acc[mi][ni][1] - th0) * sc0;
            v1.x = (acc[mi][ni][2] - th1) * sc1;
            v1.y = (acc[mi][ni][3] - th1) * sc1;
            *(float2*)&g_tl[(size_t)nr0 * BATCH + bc] = v0;
            *(float2*)&g_tl[(size_t)nr1 * BATCH + bc] = v1;
        }
    }
}

// ---------------------------------------------------------------------------
// Kernel 3: one (tree, batch) pair per thread. Block = 8 trees x 32 batches.
// ---------------------------------------------------------------------------
#define TT 8    // trees per block
#define BB 32   // batches per block

__global__ void __launch_bounds__(256, 4)
leaf_kernel(const float* __restrict__ response,  // [512][3][64]
            float* __restrict__ out)             // [512][1536]
{
    __shared__ float4 rsp4[TT * 48];
    __shared__ float  sout[BB][TT * 3 + 3];

    const int t0   = blockIdx.x * TT;
    const int b0   = blockIdx.y * BB;
    const int tid  = threadIdx.x;
    const int lane = tid & 31;
    const int w    = tid >> 5;

    for (int i = tid; i < TT * 48; i += 256)
        rsp4[i] = ((const float4*)response)[(size_t)t0 * 48 + i];
    __syncthreads();

    const int t = t0 + w;
    const int b = b0 + lane;

    float a[DEPTH], bb[DEPTH];
    #pragma unroll
    for (int d = 0; d < DEPTH; d++) {
        float v = g_tl[(size_t)(t * DEPTH + d) * BATCH + b];
        float x = 0.5f * v;
        a[d]  = fminf(fmaxf(0.5f + x, -0.5f), 1.5f);
        bb[d] = fminf(fmaxf(0.5f - x, -0.5f), 1.5f);
    }

    float w8[8];
    w8[0] = 1.0f;
    #pragma unroll
    for (int d = 0; d < 3; d++) {
        const int sz = 1 << d;
        #pragma unroll
        for (int i = sz - 1; i >= 0; i--) {
            w8[i + sz] = w8[i] * bb[d];
            w8[i]      = w8[i] * a[d];
        }
    }
    float q8[8];
    q8[0] = 1.0f;
    #pragma unroll
    for (int e = 0; e < 3; e++) {
        const int sz = 1 << e;
        #pragma unroll
        for (int i = sz - 1; i >= 0; i--) {
            q8[i + sz] = q8[i] * bb[3 + e];
            q8[i]      = q8[i] * a[3 + e];
        }
    }

    const float4* rp = &rsp4[w * 48];
    float o0 = 0.0f, o1 = 0.0f, o2 = 0.0f;
    #pragma unroll
    for (int j = 0; j < 8; j++) {
        float4 r00 = rp[j * 2],      r01 = rp[j * 2 + 1];
        float4 r10 = rp[16 + j * 2], r11 = rp[16 + j * 2 + 1];
        float4 r20 = rp[32 + j * 2], r21 = rp[32 + j * 2 + 1];
        float s0 = w8[0]*r00.x + w8[1]*r00.y + w8[2]*r00.z + w8[3]*r00.w
                 + w8[4]*r01.x + w8[5]*r01.y + w8[6]*r01.z + w8[7]*r01.w;
        float s1 = w8[0]*r10.x + w8[1]*r10.y + w8[2]*r10.z + w8[3]*r10.w
                 + w8[4]*r11.x + w8[5]*r11.y + w8[6]*r11.z + w8[7]*r11.w;
        float s2 = w8[0]*r20.x + w8[1]*r20.y + w8[2]*r20.z + w8[3]*r20.w
                 + w8[4]*r21.x + w8[5]*r21.y + w8[6]*r21.z + w8[7]*r21.w;
        o0 = fmaf(q8[j], s0, o0);
        o1 = fmaf(q8[j], s1, o1);
        o2 = fmaf(q8[j], s2, o2);
    }

    sout[lane][w * 3 + 0] = o0;
    sout[lane][w * 3 + 1] = o1;
    sout[lane][w * 3 + 2] = o2;
    __syncthreads();

    if (tid < (BB * TT * 3) / 4) {
        int row = tid / 6;
        int col = tid % 6;
        float4 v;
        v.x = sout[row][col * 4 + 0];
        v.y = sout[row][col * 4 + 1];
        v.z = sout[row][col * 4 + 2];
        v.w = sout[row][col * 4 + 3];
        *(float4*)&out[(size_t)(b0 + row) * (NTREES * TDIM) + t0 * 3 + col * 4] = v;
    }
}

// ---------------------------------------------------------------------------
extern "C" void kernel_launch(void* const* d_in, const int* in_sizes, int n_in,
                              void* d_out, int out_size)
{
    const float* input    = (const float*)d_in[0];  // [512][256]
    const float* fa       = (const float*)d_in[1];  // [256][3072]
    const float* thr      = (const float*)d_in[2];  // [512][6]
    const float* ltemp    = (const float*)d_in[3];  // [512][6]
    const float* response = (const float*)d_in[4];  // [512][3][64]
    float* out = (float*)d_out;                     // [512][1536]

    cudaFuncSetAttribute(gemm_hmma_kernel,
                         cudaFuncAttributeMaxDynamicSharedMemorySize, SM_TOTAL);

    prep_kernel<<<ENT_BLOCKS + SPL_BLOCKS, 128>>>(fa, input);

    dim3 g2(NCOLS / 128, BATCH / 64);
    gemm_hmma_kernel<<<g2, 256, SM_TOTAL>>>(thr, ltemp);

    dim3 g3(NTREES / TT, BATCH / BB);
    leaf_kernel<<<g3, 256>>>(response, out);
}

// round 16
// speedup vs baseline: 1.4046x; 1.0015x over previous
#include <cuda_runtime.h>
#include <cuda_fp16.h>
#include <math.h>
#include <stdint.h>

// Problem constants
#define F_IN   256
#define NTREES 512
#define DEPTH  6
#define TDIM   3
#define BATCH  512
#define NCOLS  (NTREES * DEPTH)   // 3072
#define KSA    256                // A stored K (fp16)
#define KSB    256                // B stored K (fp16)
#define KV     256                // GEMM K (pure fp16; calibrated ~1e-4)

// Scratch (device globals)
__device__ __half g_A[NCOLS * KSA];    // W^T fp16
__device__ __half g_B[BATCH * KSB];    // input fp16
__device__ __half g_tl[NCOLS * BATCH]; // thresholded logits fp16 [3072][512]

// ---------------------------------------------------------------------------
// Portable tensor-path helpers (sm_80+ baseline; ptxas targets plain sm_103)
// ---------------------------------------------------------------------------
__device__ __forceinline__ uint32_t smem_u32(const void* p) {
    uint32_t a;
    asm("{ .reg .u64 t; cvta.to.shared.u64 t, %1; cvt.u32.u64 %0, t; }" : "=r"(a) : "l"(p));
    return a;
}
__device__ __forceinline__ void cpa16(uint32_t dst, const void* src) {
    asm volatile("cp.async.cg.shared.global [%0], [%1], 16;" :: "r"(dst), "l"(src));
}
__device__ __forceinline__ void ldsm4(uint32_t* r, uint32_t addr) {
    asm volatile("ldmatrix.sync.aligned.m8n8.x4.shared.b16 {%0,%1,%2,%3}, [%4];"
                 : "=r"(r[0]), "=r"(r[1]), "=r"(r[2]), "=r"(r[3]) : "r"(addr));
}
__device__ __forceinline__ void mma16816(float* c, const uint32_t* a,
                                         uint32_t b0, uint32_t b1) {
    asm volatile(
        "mma.sync.aligned.m16n8k16.row.col.f32.f16.f16.f32 "
        "{%0,%1,%2,%3}, {%4,%5,%6,%7}, {%8,%9}, {%0,%1,%2,%3};"
        : "+f"(c[0]), "+f"(c[1]), "+f"(c[2]), "+f"(c[3])
        : "r"(a[0]), "r"(a[1]), "r"(a[2]), "r"(a[3]), "r"(b0), "r"(b1));
}
// 128B-row XOR swizzle: 16B chunk index ^= (row & 7)
__device__ __forceinline__ uint32_t swz(uint32_t base, int row, int kbyte) {
    uint32_t off = (uint32_t)(row * 128 + kbyte);
    return base + (off ^ ((off >> 3) & 0x70));
}

// ---------------------------------------------------------------------------
// Kernel 1: fused prep (256 threads/block).
// Blocks [0, 384): exact 1.5-entmax, one warp per column (8 cols/block)
//   -> g_A fp16. Newton on g(tau)=sum relu(z-tau)^2-1 (convex => monotone).
//   32B row segments => full-sector coalescing on the fa load.
// Blocks [384, 512): input fp32 -> fp16 into g_B.
// ---------------------------------------------------------------------------
#define CPB 8
#define ENT_BLOCKS (NCOLS / CPB)           // 384
#define SPL_BLOCKS (BATCH * F_IN / 1024)   // 128

__global__ void __launch_bounds__(256, 4)
prep_kernel(const float* __restrict__ fa,
            const float* __restrict__ input)
{
    const int tid = threadIdx.x;

    if (blockIdx.x >= ENT_BLOCKS) {
        // ---- input -> fp16 rows of g_B ----
        int i = (blockIdx.x - ENT_BLOCKS) * 256 + tid;  // float4 units
        int b = i >> 6;
        int r = i & 63;                                  // k = 4*r
        float4 v = ((const float4*)input)[i];
        __half2 h01 = __float22half2_rn(make_float2(v.x, v.y));
        __half2 h23 = __float22half2_rn(make_float2(v.z, v.w));
        *(uint2*)(g_B + b * KSB + r * 4) =
            make_uint2(*(uint32_t*)&h01, *(uint32_t*)&h23);
        return;
    }

    // ---- entmax: warp per column, 8 columns per block ----
    __shared__ float s[CPB][260];

    const int c0   = blockIdx.x * CPB;
    const int lane = tid & 31;
    const int w    = tid >> 5;       // column within block (0..7)

    // coalesced load (32B full sectors), transposed store
    #pragma unroll
    for (int i = 0; i < 8; i++) {
        int e = tid + i * 256;
        int c = e & 7;
        int r = e >> 3;
        s[c][r] = 0.5f * fa[r * NCOLS + c0 + c];
    }
    __syncthreads();

    // lane owns k = 8*lane .. 8*lane+7
    float4 za = *(const float4*)&s[w][lane * 8];
    float4 zb = *(const float4*)&s[w][lane * 8 + 4];

    // column max
    float mx = fmaxf(fmaxf(fmaxf(za.x, za.y), fmaxf(za.z, za.w)),
                     fmaxf(fmaxf(zb.x, zb.y), fmaxf(zb.z, zb.w)));
    #pragma unroll
    for (int off = 16; off > 0; off >>= 1)
        mx = fmaxf(mx, __shfl_xor_sync(0xffffffffu, mx, off));
    za.x -= mx; za.y -= mx; za.z -= mx; za.w -= mx;
    zb.x -= mx; zb.y -= mx; zb.z -= mx; zb.w -= mx;

    // Newton: tau0 = -1 (max(z)=0); monotone from below; fast division.
    float tau = -1.0f;
    for (int it = 0; it < 9; it++) {
        float d0 = fmaxf(za.x - tau, 0.0f);
        float d1 = fmaxf(za.y - tau, 0.0f);
        float d2 = fmaxf(za.z - tau, 0.0f);
        float d3 = fmaxf(za.w - tau, 0.0f);
        float d4 = fmaxf(zb.x - tau, 0.0f);
        float d5 = fmaxf(zb.y - tau, 0.0f);
        float d6 = fmaxf(zb.z - tau, 0.0f);
        float d7 = fmaxf(zb.w - tau, 0.0f);
        float s1 = ((d0 + d1) + (d2 + d3)) + ((d4 + d5) + (d6 + d7));
        float p0 = fmaf(d1, d1, d0 * d0);
        float p1 = fmaf(d3, d3, d2 * d2);
        float p2 = fmaf(d5, d5, d4 * d4);
        float p3 = fmaf(d7, d7, d6 * d6);
        float s2 = (p0 + p1) + (p2 + p3);
        #pragma unroll
        for (int off = 16; off > 0; off >>= 1) {
            s1 += __shfl_xor_sync(0xffffffffu, s1, off);
            s2 += __shfl_xor_sync(0xffffffffu, s2, off);
        }
        tau += __fdividef(s2 - 1.0f, 2.0f * s1);
    }

    // emit fp16 weights: 8 halfs = 16B -> STG.128, coalesced
    float d0 = fmaxf(za.x - tau, 0.0f);
    float d1 = fmaxf(za.y - tau, 0.0f);
    float d2 = fmaxf(za.z - tau, 0.0f);
    float d3 = fmaxf(za.w - tau, 0.0f);
    float d4 = fmaxf(zb.x - tau, 0.0f);
    float d5 = fmaxf(zb.y - tau, 0.0f);
    float d6 = fmaxf(zb.z - tau, 0.0f);
    float d7 = fmaxf(zb.w - tau, 0.0f);

    __half2 h01 = __float22half2_rn(make_float2(d0 * d0, d1 * d1));
    __half2 h23 = __float22half2_rn(make_float2(d2 * d2, d3 * d3));
    __half2 h45 = __float22half2_rn(make_float2(d4 * d4, d5 * d5));
    __half2 h67 = __float22half2_rn(make_float2(d6 * d6, d7 * d7));

    __half* Arow = g_A + (size_t)(c0 + w) * KSA;
    *(uint4*)(Arow + lane * 8) =
        make_uint4(*(uint32_t*)&h01, *(uint32_t*)&h23,
                   *(uint32_t*)&h45, *(uint32_t*)&h67);
}

// ---------------------------------------------------------------------------
// Kernel 2: HMMA fp16 GEMM, K=256; fused threshold epilogue, fp16 tl output.
// CTA: M=128(n) x N=64(b), 8 warps of 32x32, K chunks of 64, double-buffered
// cp.async, XOR-swizzled smem, ldmatrix.x4.
// ---------------------------------------------------------------------------
#define CK 64
#define NKC (KV / CK)    // 4

#define SA0 0
#define SA1 16384
#define SB0 32768
#define SB1 40960
#define SM_TOTAL 49152

__device__ __forceinline__ void load_A_chunk(uint32_t sbase, int n0, int kc, int tid)
{
    #pragma unroll
    for (int j = 0; j < 4; j++) {
        int e = tid + j * 256;
        int row = e >> 3;
        int ch  = e & 7;
        cpa16(swz(sbase, row, ch * 16),
              g_A + (size_t)(n0 + row) * KSA + kc * CK + ch * 8);
    }
}
__device__ __forceinline__ void load_B_chunk(uint32_t sbase, int b0, int kc, int tid)
{
    #pragma unroll
    for (int j = 0; j < 2; j++) {
        int e = tid + j * 256;
        int row = e >> 3;
        int ch  = e & 7;
        cpa16(swz(sbase, row, ch * 16),
              g_B + (size_t)(b0 + row) * KSB + kc * CK + ch * 8);
    }
}

__global__ void __launch_bounds__(256, 2)
gemm_hmma_kernel(const float* __restrict__ thr,
                 const float* __restrict__ ltemp)
{
    extern __shared__ char smem[];
    const uint32_t sb = smem_u32(smem);
    const int tid  = threadIdx.x;
    const int lane = tid & 31;
    const int wid  = tid >> 5;
    const int wm   = wid >> 1;
    const int wn   = wid & 1;

    const int n0 = blockIdx.x * 128;
    const int b0 = blockIdx.y * 64;

    const uint32_t sA[2] = {sb + SA0, sb + SA1};
    const uint32_t sB[2] = {sb + SB0, sb + SB1};

    float acc[2][4][4];
    #pragma unroll
    for (int mi = 0; mi < 2; mi++)
        #pragma unroll
        for (int ni = 0; ni < 4; ni++)
            #pragma unroll
            for (int q = 0; q < 4; q++) acc[mi][ni][q] = 0.0f;

    load_A_chunk(sA[0], n0, 0, tid);
    load_B_chunk(sB[0], b0, 0, tid);
    asm volatile("cp.async.commit_group;");

    const int lane15 = lane & 15;
    const int khalf  = (lane >> 4) * 16;

    int buf = 0;
    for (int kc = 0; kc < NKC; kc++) {
        if (kc + 1 < NKC) {
            load_A_chunk(sA[buf ^ 1], n0, kc + 1, tid);
            load_B_chunk(sB[buf ^ 1], b0, kc + 1, tid);
            asm volatile("cp.async.commit_group;");
            asm volatile("cp.async.wait_group 1;");
        } else {
            asm volatile("cp.async.wait_group 0;");
        }
        __syncthreads();

        #pragma unroll
        for (int ks = 0; ks < 4; ks++) {
            const int kbyte = ks * 32 + khalf;
            uint32_t a0[4], a1[4], bq0[4], bq1[4];
            ldsm4(a0,  swz(sA[buf], wm * 32 + lane15,      kbyte));
            ldsm4(a1,  swz(sA[buf], wm * 32 + 16 + lane15, kbyte));
            ldsm4(bq0, swz(sB[buf], wn * 32 + lane15,      kbyte));
            ldsm4(bq1, swz(sB[buf], wn * 32 + 16 + lane15, kbyte));

            mma16816(acc[0][0], a0, bq0[0], bq0[2]);
            mma16816(acc[0][1], a0, bq0[1], bq0[3]);
            mma16816(acc[0][2], a0, bq1[0], bq1[2]);
            mma16816(acc[0][3], a0, bq1[1], bq1[3]);
            mma16816(acc[1][0], a1, bq0[0], bq0[2]);
            mma16816(acc[1][1], a1, bq0[1], bq0[3]);
            mma16816(acc[1][2], a1, bq1[0], bq1[2]);
            mma16816(acc[1][3], a1, bq1[1], bq1[3]);
        }
        __syncthreads();
        buf ^= 1;
    }

    const int qr = lane >> 2;
    const int qc = (lane & 3) * 2;
    #pragma unroll
    for (int mi = 0; mi < 2; mi++) {
        const int nr0 = n0 + wm * 32 + mi * 16 + qr;
        const int nr1 = nr0 + 8;
        const int t0 = nr0 / DEPTH, d0 = nr0 % DEPTH;
        const int t1 = nr1 / DEPTH, d1 = nr1 % DEPTH;
        const float th0 = thr[t0 * DEPTH + d0];
        const float sc0 = expf(-ltemp[t0 * DEPTH + d0]);
        const float th1 = thr[t1 * DEPTH + d1];
        const float sc1 = expf(-ltemp[t1 * DEPTH + d1]);
        #pragma unroll
        for (int ni = 0; ni < 4; ni++) {
            const int bc = b0 + wn * 32 + ni * 8 + qc;
            __half2 v0 = __float22half2_rn(make_float2(
                (acc[mi][ni][0] - th0) * sc0, (acc[mi][ni][1] - th0) * sc0));
            __half2 v1 = __float22half2_rn(make_float2(
                (acc[mi][ni][2] - th1) * sc1, (acc[mi][ni][3] - th1) * sc1));
            *(__half2*)&g_tl[(size_t)nr0 * BATCH + bc] = v0;
            *(__half2*)&g_tl[(size_t)nr1 * BATCH + bc] = v1;
        }
    }
}

// ---------------------------------------------------------------------------
// Kernel 3: one (tree, batch) pair per thread. Block = 8 trees x 32 batches.
// tl read as fp16 (halved traffic).
// ---------------------------------------------------------------------------
#define TT 8    // trees per block
#define BB 32   // batches per block

__global__ void __launch_bounds__(256, 4)
leaf_kernel(const float* __restrict__ response,  // [512][3][64]
            float* __restrict__ out)             // [512][1536]
{
    __shared__ float4 rsp4[TT * 48];
    __shared__ float  sout[BB][TT * 3 + 3];

    const int t0   = blockIdx.x * TT;
    const int b0   = blockIdx.y * BB;
    const int tid  = threadIdx.x;
    const int lane = tid & 31;
    const int w    = tid >> 5;

    for (int i = tid; i < TT * 48; i += 256)
        rsp4[i] = ((const float4*)response)[(size_t)t0 * 48 + i];
    __syncthreads();

    const int t = t0 + w;
    const int b = b0 + lane;

    float a[DEPTH], bb[DEPTH];
    #pragma unroll
    for (int d = 0; d < DEPTH; d++) {
        float v = __half2float(g_tl[(size_t)(t * DEPTH + d) * BATCH + b]);
        float x = 0.5f * v;
        a[d]  = fminf(fmaxf(0.5f + x, -0.5f), 1.5f);
        bb[d] = fminf(fmaxf(0.5f - x, -0.5f), 1.5f);
    }

    float w8[8];
    w8[0] = 1.0f;
    #pragma unroll
    for (int d = 0; d < 3; d++) {
        const int sz = 1 << d;
        #pragma unroll
        for (int i = sz - 1; i >= 0; i--) {
            w8[i + sz] = w8[i] * bb[d];
            w8[i]      = w8[i] * a[d];
        }
    }
    float q8[8];
    q8[0] = 1.0f;
    #pragma unroll
    for (int e = 0; e < 3; e++) {
        const int sz = 1 << e;
        #pragma unroll
        for (int i = sz - 1; i >= 0; i--) {
            q8[i + sz] = q8[i] * bb[3 + e];
            q8[i]      = q8[i] * a[3 + e];
        }
    }

    const float4* rp = &rsp4[w * 48];
    float o0 = 0.0f, o1 = 0.0f, o2 = 0.0f;
    #pragma unroll
    for (int j = 0; j < 8; j++) {
        float4 r00 = rp[j * 2],      r01 = rp[j * 2 + 1];
        float4 r10 = rp[16 + j * 2], r11 = rp[16 + j * 2 + 1];
        float4 r20 = rp[32 + j * 2], r21 = rp[32 + j * 2 + 1];
        float s0 = w8[0]*r00.x + w8[1]*r00.y + w8[2]*r00.z + w8[3]*r00.w
                 + w8[4]*r01.x + w8[5]*r01.y + w8[6]*r01.z + w8[7]*r01.w;
        float s1 = w8[0]*r10.x + w8[1]*r10.y + w8[2]*r10.z + w8[3]*r10.w
                 + w8[4]*r11.x + w8[5]*r11.y + w8[6]*r11.z + w8[7]*r11.w;
        float s2 = w8[0]*r20.x + w8[1]*r20.y + w8[2]*r20.z + w8[3]*r20.w
                 + w8[4]*r21.x + w8[5]*r21.y + w8[6]*r21.z + w8[7]*r21.w;
        o0 = fmaf(q8[j], s0, o0);
        o1 = fmaf(q8[j], s1, o1);
        o2 = fmaf(q8[j], s2, o2);
    }

    sout[lane][w * 3 + 0] = o0;
    sout[lane][w * 3 + 1] = o1;
    sout[lane][w * 3 + 2] = o2;
    __syncthreads();

    if (tid < (BB * TT * 3) / 4) {
        int row = tid / 6;
        int col = tid % 6;
        float4 v;
        v.x = sout[row][col * 4 + 0];
        v.y = sout[row][col * 4 + 1];
        v.z = sout[row][col * 4 + 2];
        v.w = sout[row][col * 4 + 3];
        *(float4*)&out[(size_t)(b0 + row) * (NTREES * TDIM) + t0 * 3 + col * 4] = v;
    }
}

// ---------------------------------------------------------------------------
extern "C" void kernel_launch(void* const* d_in, const int* in_sizes, int n_in,
                              void* d_out, int out_size)
{
    const float* input    = (const float*)d_in[0];  // [512][256]
    const float* fa       = (const float*)d_in[1];  // [256][3072]
    const float* thr      = (const float*)d_in[2];  // [512][6]
    const float* ltemp    = (const float*)d_in[3];  // [512][6]
    const float* response = (const float*)d_in[4];  // [512][3][64]
    float* out = (float*)d_out;                     // [512][1536]

    cudaFuncSetAttribute(gemm_hmma_kernel,
                         cudaFuncAttributeMaxDynamicSharedMemorySize, SM_TOTAL);

    prep_kernel<<<ENT_BLOCKS + SPL_BLOCKS, 256>>>(fa, input);

    dim3 g2(NCOLS / 128, BATCH / 64);
    gemm_hmma_kernel<<<g2, 256, SM_TOTAL>>>(thr, ltemp);

    dim3 g3(NTREES / TT, BATCH / BB);
    leaf_kernel<<<g3, 256>>>(response, out);
}

// round 17
// speedup vs baseline: 1.5567x; 1.1083x over previous
#include <cuda_runtime.h>
#include <cuda_fp16.h>
#include <math.h>
#include <stdint.h>

// Problem constants
#define F_IN   256
#define NTREES 512
#define DEPTH  6
#define TDIM   3
#define BATCH  512
#define NCOLS  (NTREES * DEPTH)   // 3072
#define KSA    256                // A stored K (fp16)
#define KSB    256                // B stored K (fp16)
#define KV     256                // GEMM K (pure fp16; calibrated ~1.3e-4)

// Scratch (device globals)
__device__ __half g_A[NCOLS * KSA];    // W^T fp16
__device__ __half g_B[BATCH * KSB];    // input fp16

// ---------------------------------------------------------------------------
// Portable tensor-path helpers (sm_80+ baseline; ptxas targets plain sm_103)
// ---------------------------------------------------------------------------
__device__ __forceinline__ uint32_t smem_u32(const void* p) {
    uint32_t a;
    asm("{ .reg .u64 t; cvta.to.shared.u64 t, %1; cvt.u32.u64 %0, t; }" : "=r"(a) : "l"(p));
    return a;
}
__device__ __forceinline__ void cpa16(uint32_t dst, const void* src) {
    asm volatile("cp.async.cg.shared.global [%0], [%1], 16;" :: "r"(dst), "l"(src));
}
__device__ __forceinline__ void ldsm4(uint32_t* r, uint32_t addr) {
    asm volatile("ldmatrix.sync.aligned.m8n8.x4.shared.b16 {%0,%1,%2,%3}, [%4];"
                 : "=r"(r[0]), "=r"(r[1]), "=r"(r[2]), "=r"(r[3]) : "r"(addr));
}
__device__ __forceinline__ void mma16816(float* c, const uint32_t* a,
                                         uint32_t b0, uint32_t b1) {
    asm volatile(
        "mma.sync.aligned.m16n8k16.row.col.f32.f16.f16.f32 "
        "{%0,%1,%2,%3}, {%4,%5,%6,%7}, {%8,%9}, {%0,%1,%2,%3};"
        : "+f"(c[0]), "+f"(c[1]), "+f"(c[2]), "+f"(c[3])
        : "r"(a[0]), "r"(a[1]), "r"(a[2]), "r"(a[3]), "r"(b0), "r"(b1));
}
// 128B-row XOR swizzle: 16B chunk index ^= (row & 7)
__device__ __forceinline__ uint32_t swz(uint32_t base, int row, int kbyte) {
    uint32_t off = (uint32_t)(row * 128 + kbyte);
    return base + (off ^ ((off >> 3) & 0x70));
}

// ---------------------------------------------------------------------------
// Kernel 1: fused prep (256 threads/block).
// Blocks [0, 384): exact 1.5-entmax, one warp per column (8 cols/block).
// Blocks [384, 512): input fp32 -> fp16 into g_B.
// ---------------------------------------------------------------------------
#define CPB 8
#define ENT_BLOCKS (NCOLS / CPB)           // 384
#define SPL_BLOCKS (BATCH * F_IN / 1024)   // 128

__global__ void __launch_bounds__(256, 4)
prep_kernel(const float* __restrict__ fa,
            const float* __restrict__ input)
{
    const int tid = threadIdx.x;

    if (blockIdx.x >= ENT_BLOCKS) {
        int i = (blockIdx.x - ENT_BLOCKS) * 256 + tid;  // float4 units
        int b = i >> 6;
        int r = i & 63;
        float4 v = ((const float4*)input)[i];
        __half2 h01 = __float22half2_rn(make_float2(v.x, v.y));
        __half2 h23 = __float22half2_rn(make_float2(v.z, v.w));
        *(uint2*)(g_B + b * KSB + r * 4) =
            make_uint2(*(uint32_t*)&h01, *(uint32_t*)&h23);
        return;
    }

    __shared__ float s[CPB][260];

    const int c0   = blockIdx.x * CPB;
    const int lane = tid & 31;
    const int w    = tid >> 5;

    #pragma unroll
    for (int i = 0; i < 8; i++) {
        int e = tid + i * 256;
        int c = e & 7;
        int r = e >> 3;
        s[c][r] = 0.5f * fa[r * NCOLS + c0 + c];
    }
    __syncthreads();

    float4 za = *(const float4*)&s[w][lane * 8];
    float4 zb = *(const float4*)&s[w][lane * 8 + 4];

    float mx = fmaxf(fmaxf(fmaxf(za.x, za.y), fmaxf(za.z, za.w)),
                     fmaxf(fmaxf(zb.x, zb.y), fmaxf(zb.z, zb.w)));
    #pragma unroll
    for (int off = 16; off > 0; off >>= 1)
        mx = fmaxf(mx, __shfl_xor_sync(0xffffffffu, mx, off));
    za.x -= mx; za.y -= mx; za.z -= mx; za.w -= mx;
    zb.x -= mx; zb.y -= mx; zb.z -= mx; zb.w -= mx;

    float tau = -1.0f;
    for (int it = 0; it < 9; it++) {
        float d0 = fmaxf(za.x - tau, 0.0f);
        float d1 = fmaxf(za.y - tau, 0.0f);
        float d2 = fmaxf(za.z - tau, 0.0f);
        float d3 = fmaxf(za.w - tau, 0.0f);
        float d4 = fmaxf(zb.x - tau, 0.0f);
        float d5 = fmaxf(zb.y - tau, 0.0f);
        float d6 = fmaxf(zb.z - tau, 0.0f);
        float d7 = fmaxf(zb.w - tau, 0.0f);
        float s1 = ((d0 + d1) + (d2 + d3)) + ((d4 + d5) + (d6 + d7));
        float p0 = fmaf(d1, d1, d0 * d0);
        float p1 = fmaf(d3, d3, d2 * d2);
        float p2 = fmaf(d5, d5, d4 * d4);
        float p3 = fmaf(d7, d7, d6 * d6);
        float s2 = (p0 + p1) + (p2 + p3);
        #pragma unroll
        for (int off = 16; off > 0; off >>= 1) {
            s1 += __shfl_xor_sync(0xffffffffu, s1, off);
            s2 += __shfl_xor_sync(0xffffffffu, s2, off);
        }
        tau += __fdividef(s2 - 1.0f, 2.0f * s1);
    }

    float d0 = fmaxf(za.x - tau, 0.0f);
    float d1 = fmaxf(za.y - tau, 0.0f);
    float d2 = fmaxf(za.z - tau, 0.0f);
    float d3 = fmaxf(za.w - tau, 0.0f);
    float d4 = fmaxf(zb.x - tau, 0.0f);
    float d5 = fmaxf(zb.y - tau, 0.0f);
    float d6 = fmaxf(zb.z - tau, 0.0f);
    float d7 = fmaxf(zb.w - tau, 0.0f);

    __half2 h01 = __float22half2_rn(make_float2(d0 * d0, d1 * d1));
    __half2 h23 = __float22half2_rn(make_float2(d2 * d2, d3 * d3));
    __half2 h45 = __float22half2_rn(make_float2(d4 * d4, d5 * d5));
    __half2 h67 = __float22half2_rn(make_float2(d6 * d6, d7 * d7));

    __half* Arow = g_A + (size_t)(c0 + w) * KSA;
    *(uint4*)(Arow + lane * 8) =
        make_uint4(*(uint32_t*)&h01, *(uint32_t*)&h23,
                   *(uint32_t*)&h45, *(uint32_t*)&h67);
}

// ---------------------------------------------------------------------------
// Kernel 2 (FUSED): HMMA fp16 GEMM (M=96=16 trees, N=64, K=256) + threshold
// + full leaf product + output store. One CTA = 16 trees x 64 batches.
// 6 warps (192 threads): wm in 0..2 (32 rows), wn in 0..1 (32 cols).
// After the GEMM, smem is reused: stl fp16 [96][66], resp [16*48 float4],
// sout [64][52]. Eliminates the g_tl round-trip and the third kernel.
// ---------------------------------------------------------------------------
#define TM  96
#define TN  64
#define CK  64
#define NKC (KV / CK)    // 4
#define NTHR 192

#define SA0 0
#define SA1 12288
#define SB0 24576
#define SB1 32768
#define SM_TOTAL 40960

// epilogue overlay offsets (within the same dynamic smem)
#define EP_STL  0                    // __half [96][66]  = 12672 B
#define EP_RSP  12672                // float4[16*48]    = 12288 B
#define EP_OUT  24960                // float [64][52]   = 13312 B -> 38272 B

__device__ __forceinline__ void load_A_chunk(uint32_t sbase, int n0, int kc, int tid)
{
    #pragma unroll
    for (int j = 0; j < 4; j++) {
        int e = tid + j * NTHR;      // 768 entries: 96 rows x 8 chunks
        int row = e >> 3;
        int ch  = e & 7;
        cpa16(swz(sbase, row, ch * 16),
              g_A + (size_t)(n0 + row) * KSA + kc * CK + ch * 8);
    }
}
__device__ __forceinline__ void load_B_chunk(uint32_t sbase, int b0, int kc, int tid)
{
    #pragma unroll
    for (int j = 0; j < 3; j++) {
        int e = tid + j * NTHR;      // 512 entries: 64 rows x 8 chunks
        if (e < 512) {
            int row = e >> 3;
            int ch  = e & 7;
            cpa16(swz(sbase, row, ch * 16),
                  g_B + (size_t)(b0 + row) * KSB + kc * CK + ch * 8);
        }
    }
}

__global__ void __launch_bounds__(NTHR, 2)
gemm_leaf_kernel(const float* __restrict__ thr,
                 const float* __restrict__ ltemp,
                 const float* __restrict__ response,  // [512][3][64]
                 float* __restrict__ out)             // [512][1536]
{
    extern __shared__ char smem[];
    const uint32_t sb = smem_u32(smem);
    const int tid  = threadIdx.x;
    const int lane = tid & 31;
    const int wid  = tid >> 5;     // 0..5
    const int wm   = wid >> 1;     // 0..2
    const int wn   = wid & 1;      // 0..1

    const int n0 = blockIdx.x * TM;        // 96 n-rows = 16 trees
    const int t0 = blockIdx.x * (TM / DEPTH);
    const int b0 = blockIdx.y * TN;

    const uint32_t sA[2] = {sb + SA0, sb + SA1};
    const uint32_t sB[2] = {sb + SB0, sb + SB1};

    float acc[2][4][4];
    #pragma unroll
    for (int mi = 0; mi < 2; mi++)
        #pragma unroll
        for (int ni = 0; ni < 4; ni++)
            #pragma unroll
            for (int q = 0; q < 4; q++) acc[mi][ni][q] = 0.0f;

    load_A_chunk(sA[0], n0, 0, tid);
    load_B_chunk(sB[0], b0, 0, tid);
    asm volatile("cp.async.commit_group;");

    const int lane15 = lane & 15;
    const int khalf  = (lane >> 4) * 16;

    int buf = 0;
    for (int kc = 0; kc < NKC; kc++) {
        if (kc + 1 < NKC) {
            load_A_chunk(sA[buf ^ 1], n0, kc + 1, tid);
            load_B_chunk(sB[buf ^ 1], b0, kc + 1, tid);
            asm volatile("cp.async.commit_group;");
            asm volatile("cp.async.wait_group 1;");
        } else {
            asm volatile("cp.async.wait_group 0;");
        }
        __syncthreads();

        #pragma unroll
        for (int ks = 0; ks < 4; ks++) {
            const int kbyte = ks * 32 + khalf;
            uint32_t a0[4], a1[4], bq0[4], bq1[4];
            ldsm4(a0,  swz(sA[buf], wm * 32 + lane15,      kbyte));
            ldsm4(a1,  swz(sA[buf], wm * 32 + 16 + lane15, kbyte));
            ldsm4(bq0, swz(sB[buf], wn * 32 + lane15,      kbyte));
            ldsm4(bq1, swz(sB[buf], wn * 32 + 16 + lane15, kbyte));

            mma16816(acc[0][0], a0, bq0[0], bq0[2]);
            mma16816(acc[0][1], a0, bq0[1], bq0[3]);
            mma16816(acc[0][2], a0, bq1[0], bq1[2]);
            mma16816(acc[0][3], a0, bq1[1], bq1[3]);
            mma16816(acc[1][0], a1, bq0[0], bq0[2]);
            mma16816(acc[1][1], a1, bq0[1], bq0[3]);
            mma16816(acc[1][2], a1, bq1[0], bq1[2]);
            mma16816(acc[1][3], a1, bq1[1], bq1[3]);
        }
        __syncthreads();
        buf ^= 1;
    }
    // all smem reads done (barrier at end of loop) -> safe to overlay

    __half* stl   = (__half*)(smem + EP_STL);    // [96][66]
    float4* rsp4  = (float4*)(smem + EP_RSP);    // [16*48]
    float*  soutp = (float*)(smem + EP_OUT);     // [64][52]

    // threshold epilogue -> stl fp16
    const int qr = lane >> 2;
    const int qc = (lane & 3) * 2;
    #pragma unroll
    for (int mi = 0; mi < 2; mi++) {
        const int nl0 = wm * 32 + mi * 16 + qr;
        const int nl1 = nl0 + 8;
        const int nr0 = n0 + nl0, nr1 = n0 + nl1;
        const int tt0 = nr0 / DEPTH, dd0 = nr0 % DEPTH;
        const int tt1 = nr1 / DEPTH, dd1 = nr1 % DEPTH;
        const float th0 = thr[tt0 * DEPTH + dd0];
        const float sc0 = expf(-ltemp[tt0 * DEPTH + dd0]);
        const float th1 = thr[tt1 * DEPTH + dd1];
        const float sc1 = expf(-ltemp[tt1 * DEPTH + dd1]);
        #pragma unroll
        for (int ni = 0; ni < 4; ni++) {
            const int bcl = wn * 32 + ni * 8 + qc;
            __half2 v0 = __float22half2_rn(make_float2(
                (acc[mi][ni][0] - th0) * sc0, (acc[mi][ni][1] - th0) * sc0));
            __half2 v1 = __float22half2_rn(make_float2(
                (acc[mi][ni][2] - th1) * sc1, (acc[mi][ni][3] - th1) * sc1));
            *(__half2*)&stl[nl0 * 66 + bcl] = v0;
            *(__half2*)&stl[nl1 * 66 + bcl] = v1;
        }
    }

    // stage response for the CTA's 16 trees (768 float4)
    {
        const float4* gr = (const float4*)response + (size_t)t0 * 48;
        #pragma unroll
        for (int j = 0; j < 4; j++)
            rsp4[tid + j * NTHR] = gr[tid + j * NTHR];
    }
    __syncthreads();

    // leaf product: 16 trees x 64 batches = 1024 pairs
    for (int idx = tid; idx < (TM / DEPTH) * TN; idx += NTHR) {
        const int tl_ = idx >> 6;       // tree local 0..15
        const int bl  = idx & 63;       // batch local

        float a[DEPTH], bb[DEPTH];
        #pragma unroll
        for (int d = 0; d < DEPTH; d++) {
            float v = __half2float(stl[(tl_ * DEPTH + d) * 66 + bl]);
            float x = 0.5f * v;
            a[d]  = fminf(fmaxf(0.5f + x, -0.5f), 1.5f);
            bb[d] = fminf(fmaxf(0.5f - x, -0.5f), 1.5f);
        }

        float w8[8];
        w8[0] = 1.0f;
        #pragma unroll
        for (int d = 0; d < 3; d++) {
            const int sz = 1 << d;
            #pragma unroll
            for (int i = sz - 1; i >= 0; i--) {
                w8[i + sz] = w8[i] * bb[d];
                w8[i]      = w8[i] * a[d];
            }
        }
        float q8[8];
        q8[0] = 1.0f;
        #pragma unroll
        for (int e = 0; e < 3; e++) {
            const int sz = 1 << e;
            #pragma unroll
            for (int i = sz - 1; i >= 0; i--) {
                q8[i + sz] = q8[i] * bb[3 + e];
                q8[i]      = q8[i] * a[3 + e];
            }
        }

        const float4* rp = &rsp4[tl_ * 48];
        float o0 = 0.0f, o1 = 0.0f, o2 = 0.0f;
        #pragma unroll
        for (int j = 0; j < 8; j++) {
            float4 r00 = rp[j * 2],      r01 = rp[j * 2 + 1];
            float4 r10 = rp[16 + j * 2], r11 = rp[16 + j * 2 + 1];
            float4 r20 = rp[32 + j * 2], r21 = rp[32 + j * 2 + 1];
            float s0 = w8[0]*r00.x + w8[1]*r00.y + w8[2]*r00.z + w8[3]*r00.w
                     + w8[4]*r01.x + w8[5]*r01.y + w8[6]*r01.z + w8[7]*r01.w;
            float s1 = w8[0]*r10.x + w8[1]*r10.y + w8[2]*r10.z + w8[3]*r10.w
                     + w8[4]*r11.x + w8[5]*r11.y + w8[6]*r11.z + w8[7]*r11.w;
            float s2 = w8[0]*r20.x + w8[1]*r20.y + w8[2]*r20.z + w8[3]*r20.w
                     + w8[4]*r21.x + w8[5]*r21.y + w8[6]*r21.z + w8[7]*r21.w;
            o0 = fmaf(q8[j], s0, o0);
            o1 = fmaf(q8[j], s1, o1);
            o2 = fmaf(q8[j], s2, o2);
        }

        soutp[bl * 52 + tl_ * 3 + 0] = o0;
        soutp[bl * 52 + tl_ * 3 + 1] = o1;
        soutp[bl * 52 + tl_ * 3 + 2] = o2;
    }
    __syncthreads();

    // coalesced output: 64 rows x 48 floats = 768 float4
    #pragma unroll
    for (int j = 0; j < 4; j++) {
        int e = tid + j * NTHR;
        int row = e / 12;
        int col = e % 12;
        float4 v;
        v.x = soutp[row * 52 + col * 4 + 0];
        v.y = soutp[row * 52 + col * 4 + 1];
        v.z = soutp[row * 52 + col * 4 + 2];
        v.w = soutp[row * 52 + col * 4 + 3];
        *(float4*)&out[(size_t)(b0 + row) * (NTREES * TDIM) + t0 * 3 + col * 4] = v;
    }
}

// ---------------------------------------------------------------------------
extern "C" void kernel_launch(void* const* d_in, const int* in_sizes, int n_in,
                              void* d_out, int out_size)
{
    const float* input    = (const float*)d_in[0];  // [512][256]
    const float* fa       = (const float*)d_in[1];  // [256][3072]
    const float* thr      = (const float*)d_in[2];  // [512][6]
    const float* ltemp    = (const float*)d_in[3];  // [512][6]
    const float* response = (const float*)d_in[4];  // [512][3][64]
    float* out = (float*)d_out;                     // [512][1536]

    cudaFuncSetAttribute(gemm_leaf_kernel,
                         cudaFuncAttributeMaxDynamicSharedMemorySize, SM_TOTAL);

    prep_kernel<<<ENT_BLOCKS + SPL_BLOCKS, 256>>>(fa, input);

    dim3 g2(NCOLS / TM, BATCH / TN);   // 32 x 8
    gemm_leaf_kernel<<<g2, NTHR, SM_TOTAL>>>(thr, ltemp, response, out);
}